// round 1
// baseline (speedup 1.0000x reference)
#include <cuda_runtime.h>

#define NN 512
#define GG 60
#define KK 13

// ---------------- scratch (device globals; allocation-free) ----------------
__device__ float g_X0 [GG * 32  * NN];   // feats transposed  [G,C,N]
__device__ float g_H  [GG * 256 * NN];   // hidden 256        [G,O,N]
__device__ float g_R  [GG * 512 * NN];   // hidden 512        [G,O,N]
__device__ float g_E  [GG * 32  * NN];   // conv_out result   [G,O,N]
__device__ float g_Wt_in [32  * KK * 256];
__device__ float g_Wt_r1 [256 * KK * 512];
__device__ float g_Wt_r2 [512 * KK * 256];
__device__ float g_Wt_out[256 * KK * 32];

// ---------------- transpose feats [N,C,G] -> [G,C,N] ----------------
__global__ void k_transpose_in(const float* __restrict__ feats) {
    int idx = blockIdx.x * blockDim.x + threadIdx.x;
    const int total = NN * 32 * GG;
    if (idx >= total) return;
    int g = idx % GG;
    int c = (idx / GG) % 32;
    int n = idx / (GG * 32);
    g_X0[(g * 32 + c) * NN + n] = feats[idx];
}

// ---------------- transpose W [O,C,K] -> Wt [(c*K+k), O] ----------------
__global__ void k_wt(const float* __restrict__ W, float* __restrict__ Wt,
                     int O, int CK) {
    int idx = blockIdx.x * blockDim.x + threadIdx.x;
    if (idx >= O * CK) return;
    int o  = idx / CK;
    int ck = idx % CK;
    Wt[ck * O + o] = W[idx];
}

// ---------------- g-batched gather-GEMM ----------------
// out[g,o,n] (+)= sum_{ck} X[nei[g,k], c, n] * Wt[ck, o] + b[o]
// MODE 0: store, MODE 1: relu+store, MODE 2: accumulate into out
template <int MODE>
__global__ void __launch_bounds__(256)
k_comb(const float* __restrict__ X, const float* __restrict__ Wt,
       const float* __restrict__ b, const int* __restrict__ nei,
       float* __restrict__ out, int C, int O) {
    const int CK = C * KK;
    __shared__ float As[16][64];
    __shared__ float Bs[16][64];
    __shared__ int   s_nei[KK];

    const int tid = threadIdx.x;
    const int bn0 = blockIdx.x * 64;
    const int bo0 = blockIdx.y * 64;
    const int g   = blockIdx.z;

    if (tid < KK) s_nei[tid] = nei[g * KK + tid];
    __syncthreads();

    const int tx = tid & 15;   // n microtile
    const int ty = tid >> 4;   // o microtile
    float acc[4][4] = {};

    for (int ck0 = 0; ck0 < CK; ck0 += 16) {
        // ---- load A tile: 16 x 64 (n contiguous) ----
        #pragma unroll
        for (int s = 0; s < 4; s++) {
            int l   = tid + s * 256;
            int ckr = l >> 6;
            int nn  = l & 63;
            int ck  = ck0 + ckr;
            int c   = ck / KK;
            int k   = ck - c * KK;
            As[ckr][nn] = X[(s_nei[k] * C + c) * NN + bn0 + nn];
        }
        // ---- load B tile: 16 x 64 (o contiguous) ----
        #pragma unroll
        for (int s = 0; s < 4; s++) {
            int l   = tid + s * 256;
            int ckr = l >> 6;
            int oo  = l & 63;
            int o   = bo0 + oo;
            Bs[ckr][oo] = (o < O) ? Wt[(ck0 + ckr) * O + o] : 0.0f;
        }
        __syncthreads();

        #pragma unroll
        for (int kk = 0; kk < 16; kk++) {
            float4 av = *(const float4*)&As[kk][tx * 4];
            float4 bv = *(const float4*)&Bs[kk][ty * 4];
            float a[4] = {av.x, av.y, av.z, av.w};
            float bb[4] = {bv.x, bv.y, bv.z, bv.w};
            #pragma unroll
            for (int i = 0; i < 4; i++)
                #pragma unroll
                for (int j = 0; j < 4; j++)
                    acc[i][j] += a[i] * bb[j];
        }
        __syncthreads();
    }

    #pragma unroll
    for (int j = 0; j < 4; j++) {
        int o = bo0 + ty * 4 + j;
        if (o >= O) continue;
        float bias = b[o];
        #pragma unroll
        for (int i = 0; i < 4; i++) {
            int n = bn0 + tx * 4 + i;
            float v = acc[i][j] + bias;
            if (MODE == 1) v = fmaxf(v, 0.0f);
            size_t idx = ((size_t)g * O + o) * NN + n;
            if (MODE == 2) out[idx] += v;
            else           out[idx] = v;
        }
    }
}

// ---------------- epilogue: residual + mean + norms + output ----------------
// out layout: [ feats_inv (N*32) | feats_eqv (N*32*G) ]
__global__ void k_final(const float* __restrict__ feats, float* __restrict__ out) {
    const int n   = blockIdx.x;
    const int tid = threadIdx.x;   // 256 threads
    __shared__ float s_eqv[32][GG];
    __shared__ float s_inv[32];
    __shared__ float s_ng[GG];
    __shared__ float s_ninv;

    for (int idx = tid; idx < 32 * GG; idx += 256) {
        int c = idx / GG;
        int g = idx % GG;
        s_eqv[c][g] = g_E[(g * 32 + c) * NN + n] + feats[(n * 32 + c) * GG + g];
    }
    __syncthreads();

    if (tid < 32) {
        float sum = 0.0f;
        #pragma unroll 4
        for (int g = 0; g < GG; g++) sum += s_eqv[tid][g];
        s_inv[tid] = sum * (1.0f / GG);
    }
    if (tid >= 64 && tid < 64 + GG) {
        int g = tid - 64;
        float q = 0.0f;
        #pragma unroll
        for (int c = 0; c < 32; c++) { float v = s_eqv[c][g]; q += v * v; }
        s_ng[g] = fmaxf(sqrtf(q), 1e-4f);
    }
    __syncthreads();
    if (tid == 0) {
        float q = 0.0f;
        #pragma unroll
        for (int c = 0; c < 32; c++) q += s_inv[c] * s_inv[c];
        s_ninv = fmaxf(sqrtf(q), 1e-4f);
    }
    __syncthreads();

    if (tid < 32) out[n * 32 + tid] = s_inv[tid] / s_ninv;
    for (int idx = tid; idx < 32 * GG; idx += 256) {
        int c = idx / GG;
        int g = idx % GG;
        out[NN * 32 + (n * 32 + c) * GG + g] = s_eqv[c][g] / s_ng[g];
    }
}

// ---------------- launch ----------------
extern "C" void kernel_launch(void* const* d_in, const int* in_sizes, int n_in,
                              void* d_out, int out_size) {
    const float* feats = (const float*)d_in[0];
    const int*   nei   = (const int*)  d_in[1];
    const float* W_in  = (const float*)d_in[2];
    const float* b_in  = (const float*)d_in[3];
    const float* W_r1  = (const float*)d_in[4];
    const float* b_r1  = (const float*)d_in[5];
    const float* W_r2  = (const float*)d_in[6];
    const float* b_r2  = (const float*)d_in[7];
    const float* W_out = (const float*)d_in[8];
    const float* b_out = (const float*)d_in[9];
    float* out = (float*)d_out;

    void *pX0, *pH, *pR, *pE, *pWin, *pWr1, *pWr2, *pWout;
    cudaGetSymbolAddress(&pX0,   g_X0);
    cudaGetSymbolAddress(&pH,    g_H);
    cudaGetSymbolAddress(&pR,    g_R);
    cudaGetSymbolAddress(&pE,    g_E);
    cudaGetSymbolAddress(&pWin,  g_Wt_in);
    cudaGetSymbolAddress(&pWr1,  g_Wt_r1);
    cudaGetSymbolAddress(&pWr2,  g_Wt_r2);
    cudaGetSymbolAddress(&pWout, g_Wt_out);

    // 1. transpose feats -> [G,C,N]
    {
        int total = NN * 32 * GG;
        k_transpose_in<<<(total + 255) / 256, 256>>>(feats);
    }
    // 2. transpose weights
    {
        int t;
        t = 256 * 32 * KK;  k_wt<<<(t + 255) / 256, 256>>>(W_in,  (float*)pWin,  256, 32 * KK);
        t = 512 * 256 * KK; k_wt<<<(t + 255) / 256, 256>>>(W_r1,  (float*)pWr1,  512, 256 * KK);
        t = 256 * 512 * KK; k_wt<<<(t + 255) / 256, 256>>>(W_r2,  (float*)pWr2,  256, 512 * KK);
        t = 32 * 256 * KK;  k_wt<<<(t + 255) / 256, 256>>>(W_out, (float*)pWout, 32,  256 * KK);
    }
    // 3. H = comb(X0, W_in) + b_in                 [G,256,N]
    k_comb<0><<<dim3(NN / 64, 256 / 64, GG), 256>>>((const float*)pX0, (const float*)pWin,
                                                    b_in, nei, (float*)pH, 32, 256);
    // 4. R = relu(comb(H, W_r1) + b_r1)            [G,512,N]
    k_comb<1><<<dim3(NN / 64, 512 / 64, GG), 256>>>((const float*)pH, (const float*)pWr1,
                                                    b_r1, nei, (float*)pR, 256, 512);
    // 5. H += comb(R, W_r2) + b_r2                 [G,256,N]
    k_comb<2><<<dim3(NN / 64, 256 / 64, GG), 256>>>((const float*)pR, (const float*)pWr2,
                                                    b_r2, nei, (float*)pH, 512, 256);
    // 6. E = comb(H, W_out) + b_out                [G,32,N]
    k_comb<0><<<dim3(NN / 64, 1, GG), 256>>>((const float*)pH, (const float*)pWout,
                                             b_out, nei, (float*)pE, 256, 32);
    // 7. epilogue
    k_final<<<NN, 256>>>(feats, out);
}

// round 4
// speedup vs baseline: 3.2115x; 3.2115x over previous
#include <cuda_runtime.h>
#include <cuda_bf16.h>
#include <cstdint>

#define NN  512
#define GG  60
#define KKN 13

// ---------------- scratch (device globals; allocation-free) ----------------
__device__ float g_X0 [GG * NN * 32];                  // feats      [g, n, 32]
__device__ float g_H  [(size_t)GG * NN * 256];         // hidden     [g, n, 256]
__device__ float g_R  [(size_t)GG * NN * 512];         // hidden     [g, n, 512]
__device__ float g_E  [GG * NN * 32];                  // conv_out   [g, n, 32]
// weight chunk images (bf16 hi/lo): [o_blk][chunk t][row o (NM)][32]
__device__ __nv_bfloat16 g_Bh_in [256 * 32  * KKN];
__device__ __nv_bfloat16 g_Bl_in [256 * 32  * KKN];
__device__ __nv_bfloat16 g_Bh_r1 [512 * 256 * KKN];
__device__ __nv_bfloat16 g_Bl_r1 [512 * 256 * KKN];
__device__ __nv_bfloat16 g_Bh_r2 [256 * 512 * KKN];
__device__ __nv_bfloat16 g_Bl_r2 [256 * 512 * KKN];
__device__ __nv_bfloat16 g_Bh_out[32  * 256 * KKN];
__device__ __nv_bfloat16 g_Bl_out[32  * 256 * KKN];

// ---------------- helpers ----------------
__device__ __forceinline__ uint32_t smem_u32(const void* p) {
    uint32_t a;
    asm("{ .reg .u64 t; cvta.to.shared.u64 t, %1; cvt.u32.u64 %0, t; }" : "=r"(a) : "l"(p));
    return a;
}
__device__ __forceinline__ uint32_t pk2(float x, float y) {
    __nv_bfloat162 t = __floats2bfloat162_rn(x, y);
    return *reinterpret_cast<uint32_t*>(&t);
}
__device__ __forceinline__ void ldsm4(uint32_t a, uint32_t r[4]) {
    asm volatile("ldmatrix.sync.aligned.m8n8.x4.shared.b16 {%0,%1,%2,%3}, [%4];"
        : "=r"(r[0]), "=r"(r[1]), "=r"(r[2]), "=r"(r[3]) : "r"(a));
}
__device__ __forceinline__ void mma_bf(float d[4], const uint32_t a[4], const uint32_t b[2]) {
    asm volatile("mma.sync.aligned.m16n8k16.row.col.f32.bf16.bf16.f32 "
        "{%0,%1,%2,%3}, {%4,%5,%6,%7}, {%8,%9}, {%0,%1,%2,%3};"
        : "+f"(d[0]), "+f"(d[1]), "+f"(d[2]), "+f"(d[3])
        : "r"(a[0]), "r"(a[1]), "r"(a[2]), "r"(a[3]), "r"(b[0]), "r"(b[1]));
}
#define CP_ASYNC16(saddr, gptr) \
    asm volatile("cp.async.ca.shared.global [%0], [%1], 16;" :: "r"(saddr), "l"(gptr) : "memory")
#define CP_COMMIT()  asm volatile("cp.async.commit_group;" ::: "memory")
#define CP_WAIT0()   asm volatile("cp.async.wait_group 0;" ::: "memory")

// ---------------- prep kernels ----------------
__global__ void k_transpose_in(const float* __restrict__ feats) {
    int idx = blockIdx.x * blockDim.x + threadIdx.x;
    const int total = GG * NN * 32;
    if (idx >= total) return;
    int g = idx / (NN * 32);
    int r = idx % (NN * 32);
    int n = r / 32, c = r % 32;
    g_X0[idx] = feats[(n * 32 + c) * GG + g];
}

// W[O,C,K] -> bf16 hi/lo chunk images [o_blk][t][row o%NM][32]
__global__ void k_wsplit(const float* __restrict__ W, __nv_bfloat16* __restrict__ Wh,
                         __nv_bfloat16* __restrict__ Wl, int O, int C, int NM) {
    int idx = blockIdx.x * blockDim.x + threadIdx.x;
    const int CK = C * KKN;
    if (idx >= O * CK) return;
    int o = idx / CK, ck = idx % CK;
    int k = ck / C, c = ck % C;
    float v = W[(o * C + c) * KKN + k];
    __nv_bfloat16 h = __float2bfloat16(v);
    float lo = v - __bfloat162float(h);
    int T = CK / 32, t = ck / 32, j = ck % 32;
    int ob = o / NM, row = o % NM;
    size_t di = ((size_t)(ob * T + t) * NM + row) * 32 + j;
    Wh[di] = h;
    Wl[di] = __float2bfloat16(lo);
}

// ---------------- bf16x3 mma.sync gather-GEMM ----------------
// D[n,o] = sum_{k,c} X[(nei[g,k]*NN+n)*C + c] * W[o][k*C+c]
// MODE 0: store(+bias), 1: relu(+bias), 2: out += (D + bias)
template <int C, int O, int NM, int MODE>
__global__ void __launch_bounds__(256)
k_gemm(const float* __restrict__ X, const __nv_bfloat16* __restrict__ Bhg,
       const __nv_bfloat16* __restrict__ Blg, const float* __restrict__ b,
       const int* __restrict__ nei, float* __restrict__ out) {
    constexpr int CK  = C * KKN;
    constexpr int T   = CK / 32;
    constexpr int WGN = NM / 32;        // warps along o
    constexpr int WGM = 8 / WGN;        // warps along n
    constexpr int WTM = 128 / WGM;      // warp tile m (64 or 16)
    constexpr int MT  = WTM / 16;
    constexpr int NT  = 4;              // warp tile n = 32
    constexpr int A_BYTES = 128 * 80;   // 128 rows x 32 bf16, stride 80B
    constexpr int B_BYTES = NM * 80;
    constexpr int SSZ  = 2 * A_BYTES + 2 * B_BYTES;
    constexpr int NF4B = NM * 4;        // 16B transfers per B region

    extern __shared__ char smem[];
    __shared__ int   s_nei[KKN];
    __shared__ float s_bias[NM];

    const int tid = threadIdx.x;
    const int g   = blockIdx.z;
    const int n0  = blockIdx.x * 128;
    const int o0  = blockIdx.y * NM;
    const uint32_t sb = smem_u32(smem);

    if (tid < KKN) s_nei[tid] = nei[g * KKN + tid];
    if (tid < NM)  s_bias[tid] = b[o0 + tid];
    __syncthreads();

    const int lane  = tid & 31;
    const int warp  = tid >> 5;
    const int m_off = (warp % WGM) * WTM;
    const int o_off = (warp / WGM) * 32;
    const int row2  = tid >> 1;         // A load: 2 threads per row
    const int part  = tid & 1;

    float acc[MT][NT][4];
    #pragma unroll
    for (int mt = 0; mt < MT; mt++)
        #pragma unroll
        for (int nt = 0; nt < NT; nt++)
            #pragma unroll
            for (int q = 0; q < 4; q++) acc[mt][nt][q] = 0.0f;

    float4 ar[4];

    auto loadA = [&](int t) {
        int k = (t * 32) / C, c0 = (t * 32) % C;
        const float* src = X + ((size_t)(s_nei[k] * NN + n0) + row2) * C + c0 + part * 16;
        const float4* s4 = (const float4*)src;
        ar[0] = s4[0]; ar[1] = s4[1]; ar[2] = s4[2]; ar[3] = s4[3];
    };
    auto storeA = [&](int s) {
        char* ah = smem + s * SSZ + row2 * 80 + part * 32;
        char* al = ah + A_BYTES;
        #pragma unroll
        for (int j = 0; j < 4; j++) {
            float4 v = ar[j];
            float hx = __bfloat162float(__float2bfloat16(v.x));
            float hy = __bfloat162float(__float2bfloat16(v.y));
            float hz = __bfloat162float(__float2bfloat16(v.z));
            float hw = __bfloat162float(__float2bfloat16(v.w));
            uint2 hv = make_uint2(pk2(hx, hy), pk2(hz, hw));
            uint2 lv = make_uint2(pk2(v.x - hx, v.y - hy), pk2(v.z - hz, v.w - hw));
            *(uint2*)(ah + j * 8) = hv;
            *(uint2*)(al + j * 8) = lv;
        }
    };
    auto copyB = [&](int t, int s) {
        const __nv_bfloat16* srch = Bhg + (size_t)(blockIdx.y * T + t) * NM * 32;
        const __nv_bfloat16* srcl = Blg + (size_t)(blockIdx.y * T + t) * NM * 32;
        uint32_t bs = sb + s * SSZ + 2 * A_BYTES;
        #pragma unroll
        for (int i = 0; i < (NF4B + 255) / 256; i++) {
            int lin = tid + i * 256;
            if ((NF4B % 256) && lin >= NF4B) break;
            uint32_t sa = bs + (lin >> 2) * 80 + (lin & 3) * 16;
            CP_ASYNC16(sa, srch + lin * 8);
            CP_ASYNC16(sa + B_BYTES, srcl + lin * 8);
        }
        CP_COMMIT();
    };
    auto compute = [&](int s) {
        uint32_t aB = sb + s * SSZ;
        uint32_t bB = aB + 2 * A_BYTES;
        #pragma unroll
        for (int kh = 0; kh < 2; kh++) {
            uint32_t ah[MT][4], al[MT][4];
            uint32_t bh[NT][2], bl[NT][2];
            #pragma unroll
            for (int mt = 0; mt < MT; mt++) {
                uint32_t ad = aB + (uint32_t)((m_off + mt * 16 + (lane & 15)) * 80
                                              + (kh * 16 + ((lane >> 4) & 1) * 8) * 2);
                ldsm4(ad, ah[mt]);
                ldsm4(ad + A_BYTES, al[mt]);
            }
            #pragma unroll
            for (int p = 0; p < 2; p++) {
                uint32_t bd = bB + (uint32_t)((o_off + p * 16 + ((lane >> 4) & 1) * 8 + (lane & 7)) * 80
                                              + (kh * 16 + ((lane >> 3) & 1) * 8) * 2);
                uint32_t r[4];
                ldsm4(bd, r);
                bh[p * 2][0] = r[0]; bh[p * 2][1] = r[1];
                bh[p * 2 + 1][0] = r[2]; bh[p * 2 + 1][1] = r[3];
                ldsm4(bd + B_BYTES, r);
                bl[p * 2][0] = r[0]; bl[p * 2][1] = r[1];
                bl[p * 2 + 1][0] = r[2]; bl[p * 2 + 1][1] = r[3];
            }
            #pragma unroll
            for (int mt = 0; mt < MT; mt++)
                #pragma unroll
                for (int nt = 0; nt < NT; nt++) {
                    mma_bf(acc[mt][nt], ah[mt], bh[nt]);
                    mma_bf(acc[mt][nt], al[mt], bh[nt]);
                    mma_bf(acc[mt][nt], ah[mt], bl[nt]);
                }
        }
    };

    // prologue
    copyB(0, 0);
    loadA(0);
    storeA(0);
    CP_WAIT0();
    __syncthreads();

    for (int t = 0; t < T; t++) {
        int s = t & 1;
        if (t + 1 < T) { copyB(t + 1, s ^ 1); loadA(t + 1); }
        compute(s);
        if (t + 1 < T) { storeA(s ^ 1); CP_WAIT0(); }
        __syncthreads();
    }

    // epilogue
    #pragma unroll
    for (int mt = 0; mt < MT; mt++) {
        int r0 = n0 + m_off + mt * 16 + (lane >> 2);
        #pragma unroll
        for (int nt = 0; nt < NT; nt++) {
            int cl = o_off + nt * 8 + (lane & 3) * 2;
            float b0v = s_bias[cl], b1v = s_bias[cl + 1];
            size_t base = ((size_t)g * NN + r0) * O + o0 + cl;
            float2 v0 = make_float2(acc[mt][nt][0] + b0v, acc[mt][nt][1] + b1v);
            float2 v1 = make_float2(acc[mt][nt][2] + b0v, acc[mt][nt][3] + b1v);
            if (MODE == 1) {
                v0.x = fmaxf(v0.x, 0.f); v0.y = fmaxf(v0.y, 0.f);
                v1.x = fmaxf(v1.x, 0.f); v1.y = fmaxf(v1.y, 0.f);
            }
            if (MODE == 2) {
                float2 p0 = *(float2*)(out + base);
                float2 p1 = *(float2*)(out + base + 8 * O);
                v0.x += p0.x; v0.y += p0.y; v1.x += p1.x; v1.y += p1.y;
            }
            *(float2*)(out + base) = v0;
            *(float2*)(out + base + 8 * O) = v1;
        }
    }
}

// ---------------- epilogue: residual + mean + norms + output ----------------
// out layout: [ feats_inv (N*32) | feats_eqv (N*32*G) ]
__global__ void k_final(const float* __restrict__ feats, float* __restrict__ out) {
    const int n   = blockIdx.x;
    const int tid = threadIdx.x;   // 256 threads
    __shared__ float s_eqv[32][GG];
    __shared__ float s_inv[32];
    __shared__ float s_ng[GG];
    __shared__ float s_ninv;

    for (int idx = tid; idx < 32 * GG; idx += 256) {
        int c = idx / GG;
        int g = idx % GG;
        s_eqv[c][g] = g_E[((size_t)g * NN + n) * 32 + c] + feats[(n * 32 + c) * GG + g];
    }
    __syncthreads();

    if (tid < 32) {
        float sum = 0.0f;
        #pragma unroll 4
        for (int g = 0; g < GG; g++) sum += s_eqv[tid][g];
        s_inv[tid] = sum * (1.0f / GG);
    }
    if (tid >= 64 && tid < 64 + GG) {
        int g = tid - 64;
        float q = 0.0f;
        #pragma unroll
        for (int c = 0; c < 32; c++) { float v = s_eqv[c][g]; q += v * v; }
        s_ng[g] = fmaxf(sqrtf(q), 1e-4f);
    }
    __syncthreads();
    if (tid == 0) {
        float q = 0.0f;
        #pragma unroll
        for (int c = 0; c < 32; c++) q += s_inv[c] * s_inv[c];
        s_ninv = fmaxf(sqrtf(q), 1e-4f);
    }
    __syncthreads();

    if (tid < 32) out[n * 32 + tid] = s_inv[tid] / s_ninv;
    for (int idx = tid; idx < 32 * GG; idx += 256) {
        int c = idx / GG;
        int g = idx % GG;
        out[NN * 32 + (n * 32 + c) * GG + g] = s_eqv[c][g] / s_ng[g];
    }
}

// ---------------- launch ----------------
extern "C" void kernel_launch(void* const* d_in, const int* in_sizes, int n_in,
                              void* d_out, int out_size) {
    const float* feats = (const float*)d_in[0];
    const int*   nei   = (const int*)  d_in[1];
    const float* W_in  = (const float*)d_in[2];
    const float* b_in  = (const float*)d_in[3];
    const float* W_r1  = (const float*)d_in[4];
    const float* b_r1  = (const float*)d_in[5];
    const float* W_r2  = (const float*)d_in[6];
    const float* b_r2  = (const float*)d_in[7];
    const float* W_out = (const float*)d_in[8];
    const float* b_out = (const float*)d_in[9];
    float* out = (float*)d_out;

    void *pX0, *pH, *pR, *pE;
    void *pBh_in, *pBl_in, *pBh_r1, *pBl_r1, *pBh_r2, *pBl_r2, *pBh_out, *pBl_out;
    cudaGetSymbolAddress(&pX0, g_X0);
    cudaGetSymbolAddress(&pH,  g_H);
    cudaGetSymbolAddress(&pR,  g_R);
    cudaGetSymbolAddress(&pE,  g_E);
    cudaGetSymbolAddress(&pBh_in,  g_Bh_in);
    cudaGetSymbolAddress(&pBl_in,  g_Bl_in);
    cudaGetSymbolAddress(&pBh_r1,  g_Bh_r1);
    cudaGetSymbolAddress(&pBl_r1,  g_Bl_r1);
    cudaGetSymbolAddress(&pBh_r2,  g_Bh_r2);
    cudaGetSymbolAddress(&pBl_r2,  g_Bl_r2);
    cudaGetSymbolAddress(&pBh_out, g_Bh_out);
    cudaGetSymbolAddress(&pBl_out, g_Bl_out);

    const int SM128 = 2 * (2 * 128 * 80 + 2 * 128 * 80);   // 81920
    const int SM32  = 2 * (2 * 128 * 80 + 2 * 32 * 80);    // 51200
    cudaFuncSetAttribute(k_gemm<32, 256, 128, 0>,  cudaFuncAttributeMaxDynamicSharedMemorySize, SM128);
    cudaFuncSetAttribute(k_gemm<256, 512, 128, 1>, cudaFuncAttributeMaxDynamicSharedMemorySize, SM128);
    cudaFuncSetAttribute(k_gemm<512, 256, 128, 2>, cudaFuncAttributeMaxDynamicSharedMemorySize, SM128);
    cudaFuncSetAttribute(k_gemm<256, 32, 32, 0>,   cudaFuncAttributeMaxDynamicSharedMemorySize, SM32);

    // 1. transpose feats -> [g, n, c]
    {
        int total = GG * NN * 32;
        k_transpose_in<<<(total + 255) / 256, 256>>>(feats);
    }
    // 2. split weights into bf16 hi/lo chunk images
    {
        int t;
        t = 256 * 32 * KKN;  k_wsplit<<<(t + 255) / 256, 256>>>(W_in,  (__nv_bfloat16*)pBh_in,  (__nv_bfloat16*)pBl_in,  256, 32,  128);
        t = 512 * 256 * KKN; k_wsplit<<<(t + 255) / 256, 256>>>(W_r1,  (__nv_bfloat16*)pBh_r1,  (__nv_bfloat16*)pBl_r1,  512, 256, 128);
        t = 256 * 512 * KKN; k_wsplit<<<(t + 255) / 256, 256>>>(W_r2,  (__nv_bfloat16*)pBh_r2,  (__nv_bfloat16*)pBl_r2,  256, 512, 128);
        t = 32 * 256 * KKN;  k_wsplit<<<(t + 255) / 256, 256>>>(W_out, (__nv_bfloat16*)pBh_out, (__nv_bfloat16*)pBl_out, 32,  256, 32);
    }
    // 3. H = comb(X0, W_in) + b_in            [g, n, 256]
    k_gemm<32, 256, 128, 0><<<dim3(4, 2, GG), 256, SM128>>>(
        (const float*)pX0, (const __nv_bfloat16*)pBh_in, (const __nv_bfloat16*)pBl_in, b_in, nei, (float*)pH);
    // 4. R = relu(comb(H, W_r1) + b_r1)       [g, n, 512]
    k_gemm<256, 512, 128, 1><<<dim3(4, 4, GG), 256, SM128>>>(
        (const float*)pH, (const __nv_bfloat16*)pBh_r1, (const __nv_bfloat16*)pBl_r1, b_r1, nei, (float*)pR);
    // 5. H += comb(R, W_r2) + b_r2            [g, n, 256]
    k_gemm<512, 256, 128, 2><<<dim3(4, 2, GG), 256, SM128>>>(
        (const float*)pR, (const __nv_bfloat16*)pBh_r2, (const __nv_bfloat16*)pBl_r2, b_r2, nei, (float*)pH);
    // 6. E = comb(H, W_out) + b_out           [g, n, 32]
    k_gemm<256, 32, 32, 0><<<dim3(4, 1, GG), 256, SM32>>>(
        (const float*)pH, (const __nv_bfloat16*)pBh_out, (const __nv_bfloat16*)pBl_out, b_out, nei, (float*)pE);
    // 7. epilogue
    k_final<<<NN, 256>>>(feats, out);
}

// round 5
// speedup vs baseline: 3.6964x; 1.1510x over previous
#include <cuda_runtime.h>
#include <cuda_bf16.h>
#include <cstdint>

#define NN  512
#define GG  60
#define KKN 13

// ---------------- scratch (device globals; allocation-free) ----------------
__device__ float g_H [(size_t)GG * NN * 256];          // hidden fp32 (residual source)
__device__ float g_E [GG * NN * 32];                   // conv_out result fp32
// split activations (bf16 hi/lo), layout [g, n, C]
__device__ __nv_bfloat16 g_Xh[GG * NN * 32],            g_Xl[GG * NN * 32];
__device__ __nv_bfloat16 g_Hh[(size_t)GG * NN * 256],   g_Hl[(size_t)GG * NN * 256];
__device__ __nv_bfloat16 g_Rh[(size_t)GG * NN * 512],   g_Rl[(size_t)GG * NN * 512];
// weight chunk images (bf16 hi/lo): [o_blk][chunk t][row o (NM)][32]
__device__ __nv_bfloat16 g_Bh_in [256 * 32  * KKN], g_Bl_in [256 * 32  * KKN];
__device__ __nv_bfloat16 g_Bh_r1 [512 * 256 * KKN], g_Bl_r1 [512 * 256 * KKN];
__device__ __nv_bfloat16 g_Bh_r2 [256 * 512 * KKN], g_Bl_r2 [256 * 512 * KKN];
__device__ __nv_bfloat16 g_Bh_out[32  * 256 * KKN], g_Bl_out[32  * 256 * KKN];

// ---------------- helpers ----------------
__device__ __forceinline__ uint32_t smem_u32(const void* p) {
    uint32_t a;
    asm("{ .reg .u64 t; cvta.to.shared.u64 t, %1; cvt.u32.u64 %0, t; }" : "=r"(a) : "l"(p));
    return a;
}
__device__ __forceinline__ uint32_t pk2(float x, float y) {
    __nv_bfloat162 t = __floats2bfloat162_rn(x, y);
    return *reinterpret_cast<uint32_t*>(&t);
}
__device__ __forceinline__ void ldsm4(uint32_t a, uint32_t r[4]) {
    asm volatile("ldmatrix.sync.aligned.m8n8.x4.shared.b16 {%0,%1,%2,%3}, [%4];"
        : "=r"(r[0]), "=r"(r[1]), "=r"(r[2]), "=r"(r[3]) : "r"(a));
}
__device__ __forceinline__ void mma_bf(float d[4], const uint32_t a[4], const uint32_t b[2]) {
    asm volatile("mma.sync.aligned.m16n8k16.row.col.f32.bf16.bf16.f32 "
        "{%0,%1,%2,%3}, {%4,%5,%6,%7}, {%8,%9}, {%0,%1,%2,%3};"
        : "+f"(d[0]), "+f"(d[1]), "+f"(d[2]), "+f"(d[3])
        : "r"(a[0]), "r"(a[1]), "r"(a[2]), "r"(a[3]), "r"(b[0]), "r"(b[1]));
}
#define CP_ASYNC16(saddr, gptr) \
    asm volatile("cp.async.ca.shared.global [%0], [%1], 16;" :: "r"(saddr), "l"(gptr) : "memory")
#define CP_COMMIT()  asm volatile("cp.async.commit_group;" ::: "memory")
#define CP_WAIT0()   asm volatile("cp.async.wait_group 0;" ::: "memory")
#define CP_WAIT1()   asm volatile("cp.async.wait_group 1;" ::: "memory")

// ---------------- prep kernels ----------------
// feats [N,C,G] -> split bf16 hi/lo [g,n,c]
__global__ void k_split_in(const float* __restrict__ feats) {
    int idx = blockIdx.x * blockDim.x + threadIdx.x;
    const int total = GG * NN * 32;
    if (idx >= total) return;
    int g = idx / (NN * 32);
    int r = idx % (NN * 32);
    int n = r / 32, c = r % 32;
    float v = feats[(n * 32 + c) * GG + g];
    __nv_bfloat16 h = __float2bfloat16(v);
    g_Xh[idx] = h;
    g_Xl[idx] = __float2bfloat16(v - __bfloat162float(h));
}

// W[O,C,K] -> bf16 hi/lo chunk images [o_blk][t][row o%NM][32]
__global__ void k_wsplit(const float* __restrict__ W, __nv_bfloat16* __restrict__ Wh,
                         __nv_bfloat16* __restrict__ Wl, int O, int C, int NM) {
    int idx = blockIdx.x * blockDim.x + threadIdx.x;
    const int CK = C * KKN;
    if (idx >= O * CK) return;
    int o = idx / CK, ck = idx % CK;
    int k = ck / C, c = ck % C;
    float v = W[(o * C + c) * KKN + k];
    __nv_bfloat16 h = __float2bfloat16(v);
    float lo = v - __bfloat162float(h);
    int T = CK / 32, t = ck / 32, j = ck % 32;
    int ob = o / NM, row = o % NM;
    size_t di = ((size_t)(ob * T + t) * NM + row) * 32 + j;
    Wh[di] = h;
    Wl[di] = __float2bfloat16(lo);
}

// ---------------- bf16x3 mma.sync gather-GEMM (pre-split operands) ----------------
// D[n,o] = sum_{k,c} X[nei[g,k]][n][c] * W[o][k*C+c] ; epilogue per flags
template <int C, int O, int NM, bool RELU, bool WF32, bool RRES, bool WSPLIT>
__global__ void __launch_bounds__(256, 2)
k_gemm(const __nv_bfloat16* __restrict__ Ah, const __nv_bfloat16* __restrict__ Al,
       const __nv_bfloat16* __restrict__ Bhg, const __nv_bfloat16* __restrict__ Blg,
       const float* __restrict__ b, const int* __restrict__ nei,
       float* __restrict__ outF, const float* __restrict__ resF,
       __nv_bfloat16* __restrict__ outH, __nv_bfloat16* __restrict__ outL) {
    constexpr int CK  = C * KKN;
    constexpr int T   = CK / 32;
    constexpr int WGN = NM / 32;        // warps along o
    constexpr int WGM = 8 / WGN;        // warps along n
    constexpr int WTM = 128 / WGM;      // warp tile m
    constexpr int MT  = WTM / 16;
    constexpr int NT  = 4;              // warp tile n = 32
    constexpr int AREG = 128 * 80;      // one A matrix region (128 rows x 64B, stride 80)
    constexpr int BREG = NM * 80;
    constexpr int SSZ  = 2 * AREG + 2 * BREG;

    extern __shared__ char smem[];
    __shared__ int   s_nei[KKN];
    __shared__ float s_bias[NM];

    const int tid = threadIdx.x;
    const int g   = blockIdx.z;
    const int n0  = blockIdx.x * 128;
    const int o0  = blockIdx.y * NM;
    const uint32_t sb = smem_u32(smem);

    if (tid < KKN) s_nei[tid] = nei[g * KKN + tid];
    if (tid < NM)  s_bias[tid] = b[o0 + tid];
    __syncthreads();

    const int lane  = tid & 31;
    const int warp  = tid >> 5;
    const int m_off = (warp % WGM) * WTM;
    const int o_off = (warp / WGM) * 32;

    float acc[MT][NT][4];
    #pragma unroll
    for (int mt = 0; mt < MT; mt++)
        #pragma unroll
        for (int nt = 0; nt < NT; nt++)
            #pragma unroll
            for (int q = 0; q < 4; q++) acc[mt][nt][q] = 0.0f;

    auto copyAB = [&](int t, int s) {
        int k = (t * 32) / C, c0 = (t * 32) % C;
        size_t abase = ((size_t)(s_nei[k] * NN + n0)) * C + c0;
        uint32_t as = sb + s * SSZ;
        #pragma unroll
        for (int i = 0; i < 2; i++) {           // 512 16B transfers per A matrix
            int lin = tid + i * 256;
            int row = lin >> 2, seg = lin & 3;
            uint32_t sa = as + row * 80 + seg * 16;
            size_t go = abase + (size_t)row * C + seg * 8;
            CP_ASYNC16(sa, Ah + go);
            CP_ASYNC16(sa + AREG, Al + go);
        }
        const __nv_bfloat16* srch = Bhg + (size_t)(blockIdx.y * T + t) * NM * 32;
        const __nv_bfloat16* srcl = Blg + (size_t)(blockIdx.y * T + t) * NM * 32;
        uint32_t bs = sb + s * SSZ + 2 * AREG;
        constexpr int NB = NM * 4;              // 16B transfers per B matrix
        #pragma unroll
        for (int i = 0; i < (NB + 255) / 256; i++) {
            int lin = tid + i * 256;
            if ((NB % 256) && lin >= NB) break;
            uint32_t sa = bs + (lin >> 2) * 80 + (lin & 3) * 16;
            CP_ASYNC16(sa, srch + lin * 8);
            CP_ASYNC16(sa + BREG, srcl + lin * 8);
        }
        CP_COMMIT();
    };

    auto compute = [&](int s) {
        uint32_t aB = sb + s * SSZ;
        uint32_t bB = aB + 2 * AREG;
        #pragma unroll
        for (int kh = 0; kh < 2; kh++) {
            uint32_t ah[MT][4], al[MT][4];
            uint32_t bh[NT][2], bl[NT][2];
            #pragma unroll
            for (int mt = 0; mt < MT; mt++) {
                uint32_t ad = aB + (uint32_t)((m_off + mt * 16 + (lane & 15)) * 80
                                              + (kh * 16 + ((lane >> 4) & 1) * 8) * 2);
                ldsm4(ad, ah[mt]);
                ldsm4(ad + AREG, al[mt]);
            }
            #pragma unroll
            for (int p = 0; p < 2; p++) {
                uint32_t bd = bB + (uint32_t)((o_off + p * 16 + ((lane >> 4) & 1) * 8 + (lane & 7)) * 80
                                              + (kh * 16 + ((lane >> 3) & 1) * 8) * 2);
                uint32_t r[4];
                ldsm4(bd, r);
                bh[p * 2][0] = r[0]; bh[p * 2][1] = r[1];
                bh[p * 2 + 1][0] = r[2]; bh[p * 2 + 1][1] = r[3];
                ldsm4(bd + BREG, r);
                bl[p * 2][0] = r[0]; bl[p * 2][1] = r[1];
                bl[p * 2 + 1][0] = r[2]; bl[p * 2 + 1][1] = r[3];
            }
            #pragma unroll
            for (int mt = 0; mt < MT; mt++)
                #pragma unroll
                for (int nt = 0; nt < NT; nt++) {
                    mma_bf(acc[mt][nt], ah[mt], bh[nt]);
                    mma_bf(acc[mt][nt], al[mt], bh[nt]);
                    mma_bf(acc[mt][nt], ah[mt], bl[nt]);
                }
        }
    };

    // 2-stage cp.async pipeline
    copyAB(0, 0);
    for (int t = 0; t < T; t++) {
        int s = t & 1;
        if (t + 1 < T) { copyAB(t + 1, s ^ 1); CP_WAIT1(); }
        else           { CP_WAIT0(); }
        __syncthreads();
        compute(s);
        __syncthreads();
    }

    // epilogue
    #pragma unroll
    for (int mt = 0; mt < MT; mt++) {
        int r0 = n0 + m_off + mt * 16 + (lane >> 2);
        #pragma unroll
        for (int nt = 0; nt < NT; nt++) {
            int cl = o_off + nt * 8 + (lane & 3) * 2;
            float b0v = s_bias[cl], b1v = s_bias[cl + 1];
            #pragma unroll
            for (int q = 0; q < 2; q++) {
                int r = r0 + q * 8;
                float vx = acc[mt][nt][q * 2 + 0] + b0v;
                float vy = acc[mt][nt][q * 2 + 1] + b1v;
                if (RELU) { vx = fmaxf(vx, 0.f); vy = fmaxf(vy, 0.f); }
                size_t ei = ((size_t)g * NN + r) * O + o0 + cl;
                if (RRES) {
                    float2 p = *(const float2*)(resF + ei);
                    vx += p.x; vy += p.y;
                }
                if (WF32) *(float2*)(outF + ei) = make_float2(vx, vy);
                if (WSPLIT) {
                    float hx = __bfloat162float(__float2bfloat16(vx));
                    float hy = __bfloat162float(__float2bfloat16(vy));
                    *(uint32_t*)(outH + ei) = pk2(hx, hy);
                    *(uint32_t*)(outL + ei) = pk2(vx - hx, vy - hy);
                }
            }
        }
    }
}

// ---------------- epilogue: residual + mean + norms + output ----------------
// out layout: [ feats_inv (N*32) | feats_eqv (N*32*G) ]
__global__ void k_final(const float* __restrict__ feats, float* __restrict__ out) {
    const int n   = blockIdx.x;
    const int tid = threadIdx.x;   // 256 threads
    __shared__ float s_eqv[32][GG];
    __shared__ float s_inv[32];
    __shared__ float s_ng[GG];
    __shared__ float s_ninv;

    for (int idx = tid; idx < 32 * GG; idx += 256) {
        int c = idx / GG;
        int g = idx % GG;
        s_eqv[c][g] = g_E[((size_t)g * NN + n) * 32 + c] + feats[(n * 32 + c) * GG + g];
    }
    __syncthreads();

    if (tid < 32) {
        float sum = 0.0f;
        #pragma unroll 4
        for (int g = 0; g < GG; g++) sum += s_eqv[tid][g];
        s_inv[tid] = sum * (1.0f / GG);
    }
    if (tid >= 64 && tid < 64 + GG) {
        int g = tid - 64;
        float q = 0.0f;
        #pragma unroll
        for (int c = 0; c < 32; c++) { float v = s_eqv[c][g]; q += v * v; }
        s_ng[g] = fmaxf(sqrtf(q), 1e-4f);
    }
    __syncthreads();
    if (tid == 0) {
        float q = 0.0f;
        #pragma unroll
        for (int c = 0; c < 32; c++) q += s_inv[c] * s_inv[c];
        s_ninv = fmaxf(sqrtf(q), 1e-4f);
    }
    __syncthreads();

    if (tid < 32) out[n * 32 + tid] = s_inv[tid] / s_ninv;
    for (int idx = tid; idx < 32 * GG; idx += 256) {
        int c = idx / GG;
        int g = idx % GG;
        out[NN * 32 + (n * 32 + c) * GG + g] = s_eqv[c][g] / s_ng[g];
    }
}

// ---------------- launch ----------------
extern "C" void kernel_launch(void* const* d_in, const int* in_sizes, int n_in,
                              void* d_out, int out_size) {
    const float* feats = (const float*)d_in[0];
    const int*   nei   = (const int*)  d_in[1];
    const float* W_in  = (const float*)d_in[2];
    const float* b_in  = (const float*)d_in[3];
    const float* W_r1  = (const float*)d_in[4];
    const float* b_r1  = (const float*)d_in[5];
    const float* W_r2  = (const float*)d_in[6];
    const float* b_r2  = (const float*)d_in[7];
    const float* W_out = (const float*)d_in[8];
    const float* b_out = (const float*)d_in[9];
    float* out = (float*)d_out;

    void *pH, *pE, *pXh, *pXl, *pHh, *pHl, *pRh, *pRl;
    void *pBh_in, *pBl_in, *pBh_r1, *pBl_r1, *pBh_r2, *pBl_r2, *pBh_out, *pBl_out;
    cudaGetSymbolAddress(&pH,  g_H);
    cudaGetSymbolAddress(&pE,  g_E);
    cudaGetSymbolAddress(&pXh, g_Xh);  cudaGetSymbolAddress(&pXl, g_Xl);
    cudaGetSymbolAddress(&pHh, g_Hh);  cudaGetSymbolAddress(&pHl, g_Hl);
    cudaGetSymbolAddress(&pRh, g_Rh);  cudaGetSymbolAddress(&pRl, g_Rl);
    cudaGetSymbolAddress(&pBh_in,  g_Bh_in);   cudaGetSymbolAddress(&pBl_in,  g_Bl_in);
    cudaGetSymbolAddress(&pBh_r1,  g_Bh_r1);   cudaGetSymbolAddress(&pBl_r1,  g_Bl_r1);
    cudaGetSymbolAddress(&pBh_r2,  g_Bh_r2);   cudaGetSymbolAddress(&pBl_r2,  g_Bl_r2);
    cudaGetSymbolAddress(&pBh_out, g_Bh_out);  cudaGetSymbolAddress(&pBl_out, g_Bl_out);

    const int SM128 = 2 * (2 * 128 * 80 + 2 * 128 * 80);   // 81920
    const int SM32  = 2 * (2 * 128 * 80 + 2 * 32 * 80);    // 51200
    cudaFuncSetAttribute((const void*)k_gemm<32, 256, 128, false, true, false, true>,
                         cudaFuncAttributeMaxDynamicSharedMemorySize, SM128);
    cudaFuncSetAttribute((const void*)k_gemm<256, 512, 128, true, false, false, true>,
                         cudaFuncAttributeMaxDynamicSharedMemorySize, SM128);
    cudaFuncSetAttribute((const void*)k_gemm<512, 256, 128, false, false, true, true>,
                         cudaFuncAttributeMaxDynamicSharedMemorySize, SM128);
    cudaFuncSetAttribute((const void*)k_gemm<256, 32, 32, false, true, false, false>,
                         cudaFuncAttributeMaxDynamicSharedMemorySize, SM32);

    // 1. split input feats -> Xh/Xl [g,n,c]
    {
        int total = GG * NN * 32;
        k_split_in<<<(total + 255) / 256, 256>>>(feats);
    }
    // 2. split weights into bf16 hi/lo chunk images
    {
        int t;
        t = 256 * 32 * KKN;  k_wsplit<<<(t + 255) / 256, 256>>>(W_in,  (__nv_bfloat16*)pBh_in,  (__nv_bfloat16*)pBl_in,  256, 32,  128);
        t = 512 * 256 * KKN; k_wsplit<<<(t + 255) / 256, 256>>>(W_r1,  (__nv_bfloat16*)pBh_r1,  (__nv_bfloat16*)pBl_r1,  512, 256, 128);
        t = 256 * 512 * KKN; k_wsplit<<<(t + 255) / 256, 256>>>(W_r2,  (__nv_bfloat16*)pBh_r2,  (__nv_bfloat16*)pBl_r2,  256, 512, 128);
        t = 32 * 256 * KKN;  k_wsplit<<<(t + 255) / 256, 256>>>(W_out, (__nv_bfloat16*)pBh_out, (__nv_bfloat16*)pBl_out, 32,  256, 32);
    }
    // 3. H = comb(X, W_in) + b_in : write fp32 H (residual src) + split Hh/Hl
    k_gemm<32, 256, 128, false, true, false, true><<<dim3(4, 2, GG), 256, SM128>>>(
        (const __nv_bfloat16*)pXh, (const __nv_bfloat16*)pXl,
        (const __nv_bfloat16*)pBh_in, (const __nv_bfloat16*)pBl_in,
        b_in, nei, (float*)pH, nullptr, (__nv_bfloat16*)pHh, (__nv_bfloat16*)pHl);
    // 4. R = relu(comb(H, W_r1) + b_r1) : split only
    k_gemm<256, 512, 128, true, false, false, true><<<dim3(4, 4, GG), 256, SM128>>>(
        (const __nv_bfloat16*)pHh, (const __nv_bfloat16*)pHl,
        (const __nv_bfloat16*)pBh_r1, (const __nv_bfloat16*)pBl_r1,
        b_r1, nei, nullptr, nullptr, (__nv_bfloat16*)pRh, (__nv_bfloat16*)pRl);
    // 5. Hnew = H + comb(R, W_r2) + b_r2 : read fp32 H residual, write split Hh/Hl
    k_gemm<512, 256, 128, false, false, true, true><<<dim3(4, 2, GG), 256, SM128>>>(
        (const __nv_bfloat16*)pRh, (const __nv_bfloat16*)pRl,
        (const __nv_bfloat16*)pBh_r2, (const __nv_bfloat16*)pBl_r2,
        b_r2, nei, nullptr, (const float*)pH, (__nv_bfloat16*)pHh, (__nv_bfloat16*)pHl);
    // 6. E = comb(Hnew, W_out) + b_out : fp32 only
    k_gemm<256, 32, 32, false, true, false, false><<<dim3(4, 1, GG), 256, SM32>>>(
        (const __nv_bfloat16*)pHh, (const __nv_bfloat16*)pHl,
        (const __nv_bfloat16*)pBh_out, (const __nv_bfloat16*)pBl_out,
        b_out, nei, (float*)pE, nullptr, nullptr, nullptr);
    // 7. epilogue
    k_final<<<NN, 256>>>(feats, out);
}

// round 7
// speedup vs baseline: 3.8669x; 1.0461x over previous
#include <cuda_runtime.h>
#include <cuda_bf16.h>
#include <cstdint>

#define NN  512
#define GG  60
#define KKN 13

// ---------------- scratch (device globals; allocation-free) ----------------
__device__ float g_E [GG * NN * 32];                   // conv_out result fp32
// split activations (bf16 hi/lo), layout [g, n, C]
__device__ __nv_bfloat16 g_Xh[GG * NN * 32],            g_Xl[GG * NN * 32];
__device__ __nv_bfloat16 g_Hh[(size_t)GG * NN * 256],   g_Hl[(size_t)GG * NN * 256];
__device__ __nv_bfloat16 g_Rh[(size_t)GG * NN * 512],   g_Rl[(size_t)GG * NN * 512];
// weight chunk images (bf16 hi/lo): [o_blk][chunk t][row o (NM)][32]
__device__ __nv_bfloat16 g_Bh_in [256 * 32  * KKN], g_Bl_in [256 * 32  * KKN];
__device__ __nv_bfloat16 g_Bh_r1 [512 * 256 * KKN], g_Bl_r1 [512 * 256 * KKN];
__device__ __nv_bfloat16 g_Bh_r2 [256 * 512 * KKN], g_Bl_r2 [256 * 512 * KKN];
__device__ __nv_bfloat16 g_Bh_out[32  * 256 * KKN], g_Bl_out[32  * 256 * KKN];

// ---------------- helpers ----------------
__device__ __forceinline__ uint32_t smem_u32(const void* p) {
    uint32_t a;
    asm("{ .reg .u64 t; cvta.to.shared.u64 t, %1; cvt.u32.u64 %0, t; }" : "=r"(a) : "l"(p));
    return a;
}
__device__ __forceinline__ uint32_t pk2(float x, float y) {
    __nv_bfloat162 t = __floats2bfloat162_rn(x, y);
    return *reinterpret_cast<uint32_t*>(&t);
}
__device__ __forceinline__ void ldsm4(uint32_t a, uint32_t r[4]) {
    asm volatile("ldmatrix.sync.aligned.m8n8.x4.shared.b16 {%0,%1,%2,%3}, [%4];"
        : "=r"(r[0]), "=r"(r[1]), "=r"(r[2]), "=r"(r[3]) : "r"(a));
}
__device__ __forceinline__ void mma_bf(float d[4], const uint32_t a[4], const uint32_t b[2]) {
    asm volatile("mma.sync.aligned.m16n8k16.row.col.f32.bf16.bf16.f32 "
        "{%0,%1,%2,%3}, {%4,%5,%6,%7}, {%8,%9}, {%0,%1,%2,%3};"
        : "+f"(d[0]), "+f"(d[1]), "+f"(d[2]), "+f"(d[3])
        : "r"(a[0]), "r"(a[1]), "r"(a[2]), "r"(a[3]), "r"(b[0]), "r"(b[1]));
}
#define CP_ASYNC16(saddr, gptr) \
    asm volatile("cp.async.ca.shared.global [%0], [%1], 16;" :: "r"(saddr), "l"(gptr) : "memory")
#define CP_COMMIT()  asm volatile("cp.async.commit_group;" ::: "memory")
#define CP_WAIT0()   asm volatile("cp.async.wait_group 0;" ::: "memory")

// ---------------- fused prep: feats split + all four weight splits ----------------
__global__ void k_prep(const float* __restrict__ feats,
                       const float* __restrict__ W0, const float* __restrict__ W1,
                       const float* __restrict__ W2, const float* __restrict__ W3) {
    int idx = blockIdx.x * blockDim.x + threadIdx.x;
    const int fTot = GG * NN * 32;
    if (idx < fTot) {
        // feats [N,C,G] -> split bf16 hi/lo [g,n,c]
        int g = idx / (NN * 32);
        int r = idx % (NN * 32);
        int n = r / 32, c = r % 32;
        float v = feats[(n * 32 + c) * GG + g];
        __nv_bfloat16 h = __float2bfloat16(v);
        g_Xh[idx] = h;
        g_Xl[idx] = __float2bfloat16(v - __bfloat162float(h));
        return;
    }
    int wi = idx - fTot;
    const int s0 = 256 * 32 * KKN;          // in
    const int s1 = 512 * 256 * KKN;         // r1
    const int s2 = 256 * 512 * KKN;         // r2
    const int s3 = 32 * 256 * KKN;          // out
    const float* W; __nv_bfloat16 *Wh, *Wl; int C, NM, li;
    if (wi < s0)                { W = W0; Wh = g_Bh_in;  Wl = g_Bl_in;  C = 32;  NM = 128; li = wi; }
    else if (wi < s0 + s1)      { W = W1; Wh = g_Bh_r1;  Wl = g_Bl_r1;  C = 256; NM = 128; li = wi - s0; }
    else if (wi < s0 + s1 + s2) { W = W2; Wh = g_Bh_r2;  Wl = g_Bl_r2;  C = 512; NM = 128; li = wi - s0 - s1; }
    else if (wi < s0 + s1 + s2 + s3)
                                { W = W3; Wh = g_Bh_out; Wl = g_Bl_out; C = 256; NM = 32;  li = wi - s0 - s1 - s2; }
    else return;
    const int CK = C * KKN;
    int o = li / CK, ck = li % CK;
    int k = ck / C, c = ck % C;
    float v = W[(o * C + c) * KKN + k];
    __nv_bfloat16 h = __float2bfloat16(v);
    int T = CK / 32, t = ck / 32, j = ck % 32;
    int ob = o / NM, row = o % NM;
    size_t di = ((size_t)(ob * T + t) * NM + row) * 32 + j;
    Wh[di] = h;
    Wl[di] = __float2bfloat16(v - __bfloat162float(h));
}

// ---------------- bf16x3 mma.sync gather-GEMM (pre-split operands) ----------------
// D[n,o] = sum_{k,c} X[nei[g,k]][n][c] * W[o][k*C+c] ; epilogue per flags
// RRES: add (resH+resL) at output location. WF32: write fp32. WSPLIT: write hi/lo.
template <int C, int O, int NM, bool RELU, bool WF32, bool RRES, bool WSPLIT>
__global__ void __launch_bounds__(256, 2)
k_gemm(const __nv_bfloat16* __restrict__ Ah, const __nv_bfloat16* __restrict__ Al,
       const __nv_bfloat16* __restrict__ Bhg, const __nv_bfloat16* __restrict__ Blg,
       const float* __restrict__ b, const int* __restrict__ nei,
       float* __restrict__ outF,
       const __nv_bfloat16* __restrict__ resH, const __nv_bfloat16* __restrict__ resL,
       __nv_bfloat16* __restrict__ outH, __nv_bfloat16* __restrict__ outL) {
    constexpr int CK  = C * KKN;
    constexpr int T   = CK / 32;
    constexpr int WGN = NM / 32;        // warps along o
    constexpr int WGM = 8 / WGN;        // warps along n
    constexpr int WTM = 128 / WGM;      // warp tile m
    constexpr int MT  = WTM / 16;
    constexpr int NT  = 4;              // warp tile n = 32
    constexpr int AREG = 128 * 80;      // one A matrix region (128 rows x 64B, stride 80)
    constexpr int BREG = NM * 80;
    constexpr int SSZ  = 2 * AREG + 2 * BREG;

    extern __shared__ char smem[];
    __shared__ int   s_nei[KKN];
    __shared__ float s_bias[NM];

    const int tid = threadIdx.x;
    const int g   = blockIdx.z;
    const int n0  = blockIdx.x * 128;
    const int o0  = blockIdx.y * NM;
    const uint32_t sb = smem_u32(smem);

    if (tid < KKN) s_nei[tid] = nei[g * KKN + tid];
    if (tid < NM)  s_bias[tid] = b[o0 + tid];
    __syncthreads();

    const int lane  = tid & 31;
    const int warp  = tid >> 5;
    const int m_off = (warp % WGM) * WTM;
    const int o_off = (warp / WGM) * 32;

    float acc[MT][NT][4];
    #pragma unroll
    for (int mt = 0; mt < MT; mt++)
        #pragma unroll
        for (int nt = 0; nt < NT; nt++)
            #pragma unroll
            for (int q = 0; q < 4; q++) acc[mt][nt][q] = 0.0f;

    auto copyAB = [&](int t, int s) {
        int k = (t * 32) / C, c0 = (t * 32) % C;
        size_t abase = ((size_t)(s_nei[k] * NN + n0)) * C + c0;
        uint32_t as = sb + s * SSZ;
        #pragma unroll
        for (int i = 0; i < 2; i++) {           // 512 16B transfers per A matrix
            int lin = tid + i * 256;
            int row = lin >> 2, seg = lin & 3;
            uint32_t sa = as + row * 80 + seg * 16;
            size_t go = abase + (size_t)row * C + seg * 8;
            CP_ASYNC16(sa, Ah + go);
            CP_ASYNC16(sa + AREG, Al + go);
        }
        const __nv_bfloat16* srch = Bhg + (size_t)(blockIdx.y * T + t) * NM * 32;
        const __nv_bfloat16* srcl = Blg + (size_t)(blockIdx.y * T + t) * NM * 32;
        uint32_t bs = sb + s * SSZ + 2 * AREG;
        constexpr int NB = NM * 4;              // 16B transfers per B matrix
        #pragma unroll
        for (int i = 0; i < (NB + 255) / 256; i++) {
            int lin = tid + i * 256;
            if ((NB % 256) && lin >= NB) break;
            uint32_t sa = bs + (lin >> 2) * 80 + (lin & 3) * 16;
            CP_ASYNC16(sa, srch + lin * 8);
            CP_ASYNC16(sa + BREG, srcl + lin * 8);
        }
        CP_COMMIT();
    };

    auto compute = [&](int s) {
        uint32_t aB = sb + s * SSZ;
        uint32_t bB = aB + 2 * AREG;
        #pragma unroll
        for (int kh = 0; kh < 2; kh++) {
            uint32_t ah[MT][4], al[MT][4];
            uint32_t bh[NT][2], bl[NT][2];
            #pragma unroll
            for (int mt = 0; mt < MT; mt++) {
                uint32_t ad = aB + (uint32_t)((m_off + mt * 16 + (lane & 15)) * 80
                                              + (kh * 16 + ((lane >> 4) & 1) * 8) * 2);
                ldsm4(ad, ah[mt]);
                ldsm4(ad + AREG, al[mt]);
            }
            #pragma unroll
            for (int p = 0; p < 2; p++) {
                uint32_t bd = bB + (uint32_t)((o_off + p * 16 + ((lane >> 4) & 1) * 8 + (lane & 7)) * 80
                                              + (kh * 16 + ((lane >> 3) & 1) * 8) * 2);
                uint32_t r[4];
                ldsm4(bd, r);
                bh[p * 2][0] = r[0]; bh[p * 2][1] = r[1];
                bh[p * 2 + 1][0] = r[2]; bh[p * 2 + 1][1] = r[3];
                ldsm4(bd + BREG, r);
                bl[p * 2][0] = r[0]; bl[p * 2][1] = r[1];
                bl[p * 2 + 1][0] = r[2]; bl[p * 2 + 1][1] = r[3];
            }
            #pragma unroll
            for (int mt = 0; mt < MT; mt++)
                #pragma unroll
                for (int nt = 0; nt < NT; nt++) {
                    mma_bf(acc[mt][nt], ah[mt], bh[nt]);
                    mma_bf(acc[mt][nt], al[mt], bh[nt]);
                    mma_bf(acc[mt][nt], ah[mt], bl[nt]);
                }
        }
    };

    // 2-stage cp.async pipeline, ONE __syncthreads per chunk:
    //   wait(copy t) -> sync (publishes stage s; proves stage s^1 compute done)
    //   -> issue copy(t+1) into s^1 -> compute(s)
    copyAB(0, 0);
    for (int t = 0; t < T; t++) {
        int s = t & 1;
        CP_WAIT0();
        __syncthreads();
        if (t + 1 < T) copyAB(t + 1, s ^ 1);
        compute(s);
    }

    // epilogue (acc regs only; no smem dependency -> no extra sync)
    #pragma unroll
    for (int mt = 0; mt < MT; mt++) {
        int r0 = n0 + m_off + mt * 16 + (lane >> 2);
        #pragma unroll
        for (int nt = 0; nt < NT; nt++) {
            int cl = o_off + nt * 8 + (lane & 3) * 2;
            float b0v = s_bias[cl], b1v = s_bias[cl + 1];
            #pragma unroll
            for (int q = 0; q < 2; q++) {
                int r = r0 + q * 8;
                float vx = acc[mt][nt][q * 2 + 0] + b0v;
                float vy = acc[mt][nt][q * 2 + 1] + b1v;
                if (RELU) { vx = fmaxf(vx, 0.f); vy = fmaxf(vy, 0.f); }
                size_t ei = ((size_t)g * NN + r) * O + o0 + cl;
                if (RRES) {
                    __nv_bfloat162 ph = *(const __nv_bfloat162*)(resH + ei);
                    __nv_bfloat162 pl = *(const __nv_bfloat162*)(resL + ei);
                    vx += __bfloat162float(ph.x) + __bfloat162float(pl.x);
                    vy += __bfloat162float(ph.y) + __bfloat162float(pl.y);
                }
                if (WF32) *(float2*)(outF + ei) = make_float2(vx, vy);
                if (WSPLIT) {
                    float hx = __bfloat162float(__float2bfloat16(vx));
                    float hy = __bfloat162float(__float2bfloat16(vy));
                    *(uint32_t*)(outH + ei) = pk2(hx, hy);
                    *(uint32_t*)(outL + ei) = pk2(vx - hx, vy - hy);
                }
            }
        }
    }
}

// ---------------- epilogue: residual + mean + norms + output ----------------
// out layout: [ feats_inv (N*32) | feats_eqv (N*32*G) ]
__global__ void k_final(const float* __restrict__ feats, float* __restrict__ out) {
    const int n   = blockIdx.x;
    const int tid = threadIdx.x;   // 256 threads
    __shared__ float s_eqv[32][GG];
    __shared__ float s_inv[32];
    __shared__ float s_ng[GG];
    __shared__ float s_ninv;

    for (int idx = tid; idx < 32 * GG; idx += 256) {
        int c = idx / GG;
        int g = idx % GG;
        s_eqv[c][g] = g_E[((size_t)g * NN + n) * 32 + c] + feats[(n * 32 + c) * GG + g];
    }
    __syncthreads();

    if (tid < 32) {
        float sum = 0.0f;
        #pragma unroll 4
        for (int g = 0; g < GG; g++) sum += s_eqv[tid][g];
        s_inv[tid] = sum * (1.0f / GG);
    }
    if (tid >= 64 && tid < 64 + GG) {
        int g = tid - 64;
        float q = 0.0f;
        #pragma unroll
        for (int c = 0; c < 32; c++) { float v = s_eqv[c][g]; q += v * v; }
        s_ng[g] = fmaxf(sqrtf(q), 1e-4f);
    }
    __syncthreads();
    if (tid == 0) {
        float q = 0.0f;
        #pragma unroll
        for (int c = 0; c < 32; c++) q += s_inv[c] * s_inv[c];
        s_ninv = fmaxf(sqrtf(q), 1e-4f);
    }
    __syncthreads();

    if (tid < 32) out[n * 32 + tid] = s_inv[tid] / s_ninv;
    for (int idx = tid; idx < 32 * GG; idx += 256) {
        int c = idx / GG;
        int g = idx % GG;
        out[NN * 32 + (n * 32 + c) * GG + g] = s_eqv[c][g] / s_ng[g];
    }
}

// ---------------- launch (single stream, linear graph) ----------------
extern "C" void kernel_launch(void* const* d_in, const int* in_sizes, int n_in,
                              void* d_out, int out_size) {
    const float* feats = (const float*)d_in[0];
    const int*   nei   = (const int*)  d_in[1];
    const float* W_in  = (const float*)d_in[2];
    const float* b_in  = (const float*)d_in[3];
    const float* W_r1  = (const float*)d_in[4];
    const float* b_r1  = (const float*)d_in[5];
    const float* W_r2  = (const float*)d_in[6];
    const float* b_r2  = (const float*)d_in[7];
    const float* W_out = (const float*)d_in[8];
    const float* b_out = (const float*)d_in[9];
    float* out = (float*)d_out;

    void *pE, *pXh, *pXl, *pHh, *pHl, *pRh, *pRl;
    void *pBh_in, *pBl_in, *pBh_r1, *pBl_r1, *pBh_r2, *pBl_r2, *pBh_out, *pBl_out;
    cudaGetSymbolAddress(&pE,  g_E);
    cudaGetSymbolAddress(&pXh, g_Xh);  cudaGetSymbolAddress(&pXl, g_Xl);
    cudaGetSymbolAddress(&pHh, g_Hh);  cudaGetSymbolAddress(&pHl, g_Hl);
    cudaGetSymbolAddress(&pRh, g_Rh);  cudaGetSymbolAddress(&pRl, g_Rl);
    cudaGetSymbolAddress(&pBh_in,  g_Bh_in);   cudaGetSymbolAddress(&pBl_in,  g_Bl_in);
    cudaGetSymbolAddress(&pBh_r1,  g_Bh_r1);   cudaGetSymbolAddress(&pBl_r1,  g_Bl_r1);
    cudaGetSymbolAddress(&pBh_r2,  g_Bh_r2);   cudaGetSymbolAddress(&pBl_r2,  g_Bl_r2);
    cudaGetSymbolAddress(&pBh_out, g_Bh_out);  cudaGetSymbolAddress(&pBl_out, g_Bl_out);

    const int SM128 = 2 * (2 * 128 * 80 + 2 * 128 * 80);   // 81920
    const int SM32  = 2 * (2 * 128 * 80 + 2 * 32 * 80);    // 51200
    cudaFuncSetAttribute((const void*)k_gemm<32, 256, 128, false, false, false, true>,
                         cudaFuncAttributeMaxDynamicSharedMemorySize, SM128);
    cudaFuncSetAttribute((const void*)k_gemm<256, 512, 128, true, false, false, true>,
                         cudaFuncAttributeMaxDynamicSharedMemorySize, SM128);
    cudaFuncSetAttribute((const void*)k_gemm<512, 256, 128, false, false, true, true>,
                         cudaFuncAttributeMaxDynamicSharedMemorySize, SM128);
    cudaFuncSetAttribute((const void*)k_gemm<256, 32, 32, false, true, false, false>,
                         cudaFuncAttributeMaxDynamicSharedMemorySize, SM32);

    // 1. fused prep: feats split + all four weight splits (one launch)
    {
        int total = GG * NN * 32
                  + (256 * 32 + 512 * 256 + 256 * 512 + 32 * 256) * KKN;
        k_prep<<<(total + 255) / 256, 256>>>(feats, W_in, W_r1, W_r2, W_out);
    }
    // 2. in: Hh/Hl = split(comb(X, W_in) + b_in)
    k_gemm<32, 256, 128, false, false, false, true><<<dim3(4, 2, GG), 256, SM128>>>(
        (const __nv_bfloat16*)pXh, (const __nv_bfloat16*)pXl,
        (const __nv_bfloat16*)pBh_in, (const __nv_bfloat16*)pBl_in,
        b_in, nei, nullptr, nullptr, nullptr,
        (__nv_bfloat16*)pHh, (__nv_bfloat16*)pHl);
    // 3. r1: Rh/Rl = split(relu(comb(H, W_r1) + b_r1))
    k_gemm<256, 512, 128, true, false, false, true><<<dim3(4, 4, GG), 256, SM128>>>(
        (const __nv_bfloat16*)pHh, (const __nv_bfloat16*)pHl,
        (const __nv_bfloat16*)pBh_r1, (const __nv_bfloat16*)pBl_r1,
        b_r1, nei, nullptr, nullptr, nullptr,
        (__nv_bfloat16*)pRh, (__nv_bfloat16*)pRl);
    // 4. r2: Hh/Hl = split((Hh+Hl) + comb(R, W_r2) + b_r2)   (in-place residual)
    k_gemm<512, 256, 128, false, false, true, true><<<dim3(4, 2, GG), 256, SM128>>>(
        (const __nv_bfloat16*)pRh, (const __nv_bfloat16*)pRl,
        (const __nv_bfloat16*)pBh_r2, (const __nv_bfloat16*)pBl_r2,
        b_r2, nei, nullptr,
        (const __nv_bfloat16*)pHh, (const __nv_bfloat16*)pHl,
        (__nv_bfloat16*)pHh, (__nv_bfloat16*)pHl);
    // 5. out: E = comb(Hnew, W_out) + b_out (fp32)
    k_gemm<256, 32, 32, false, true, false, false><<<dim3(4, 1, GG), 256, SM32>>>(
        (const __nv_bfloat16*)pHh, (const __nv_bfloat16*)pHl,
        (const __nv_bfloat16*)pBh_out, (const __nv_bfloat16*)pBl_out,
        b_out, nei, (float*)pE, nullptr, nullptr, nullptr, nullptr);
    // 6. final: residual + mean + norms
    k_final<<<NN, 256>>>(feats, out);
}

// round 8
// speedup vs baseline: 3.9363x; 1.0180x over previous
#include <cuda_runtime.h>
#include <cuda_bf16.h>
#include <cstdint>

#define NN  512
#define GG  60
#define KKN 13

// ---------------- scratch (device globals; allocation-free) ----------------
__device__ float g_E [GG * NN * 32];                   // conv_out result fp32
// split activations (bf16 hi/lo), layout [g, n, C]
__device__ __nv_bfloat16 g_Xh[GG * NN * 32],            g_Xl[GG * NN * 32];
__device__ __nv_bfloat16 g_Hh[(size_t)GG * NN * 256],   g_Hl[(size_t)GG * NN * 256];
__device__ __nv_bfloat16 g_Rh[(size_t)GG * NN * 512],   g_Rl[(size_t)GG * NN * 512];
// weight chunk images (bf16 hi/lo): [o_blk][chunk t][row o (NM)][32]
__device__ __nv_bfloat16 g_Bh_in [256 * 32  * KKN], g_Bl_in [256 * 32  * KKN];
__device__ __nv_bfloat16 g_Bh_r1 [512 * 256 * KKN], g_Bl_r1 [512 * 256 * KKN];
__device__ __nv_bfloat16 g_Bh_r2 [256 * 512 * KKN], g_Bl_r2 [256 * 512 * KKN];
__device__ __nv_bfloat16 g_Bh_out[32  * 256 * KKN], g_Bl_out[32  * 256 * KKN];

// ---------------- helpers ----------------
__device__ __forceinline__ uint32_t smem_u32(const void* p) {
    uint32_t a;
    asm("{ .reg .u64 t; cvta.to.shared.u64 t, %1; cvt.u32.u64 %0, t; }" : "=r"(a) : "l"(p));
    return a;
}
__device__ __forceinline__ uint32_t pk2(float x, float y) {
    __nv_bfloat162 t = __floats2bfloat162_rn(x, y);
    return *reinterpret_cast<uint32_t*>(&t);
}
// 64B-row swizzle: permute 16B chunk index by (row>>1)&3 -> conflict-free ldmatrix
__device__ __forceinline__ uint32_t swz(int row, int chunk) {
    return (uint32_t)(row * 64 + ((chunk ^ ((row >> 1) & 3)) * 16));
}
__device__ __forceinline__ void ldsm4(uint32_t a, uint32_t r[4]) {
    asm volatile("ldmatrix.sync.aligned.m8n8.x4.shared.b16 {%0,%1,%2,%3}, [%4];"
        : "=r"(r[0]), "=r"(r[1]), "=r"(r[2]), "=r"(r[3]) : "r"(a));
}
__device__ __forceinline__ void mma_bf(float d[4], const uint32_t a[4], const uint32_t b[2]) {
    asm volatile("mma.sync.aligned.m16n8k16.row.col.f32.bf16.bf16.f32 "
        "{%0,%1,%2,%3}, {%4,%5,%6,%7}, {%8,%9}, {%0,%1,%2,%3};"
        : "+f"(d[0]), "+f"(d[1]), "+f"(d[2]), "+f"(d[3])
        : "r"(a[0]), "r"(a[1]), "r"(a[2]), "r"(a[3]), "r"(b[0]), "r"(b[1]));
}
#define CP_ASYNC16(saddr, gptr) \
    asm volatile("cp.async.ca.shared.global [%0], [%1], 16;" :: "r"(saddr), "l"(gptr) : "memory")
#define CP_COMMIT()  asm volatile("cp.async.commit_group;" ::: "memory")
#define CP_WAIT0()   asm volatile("cp.async.wait_group 0;" ::: "memory")
#define CP_WAIT1()   asm volatile("cp.async.wait_group 1;" ::: "memory")

// ---------------- fused prep: feats split + all four weight splits ----------------
__global__ void k_prep(const float* __restrict__ feats,
                       const float* __restrict__ W0, const float* __restrict__ W1,
                       const float* __restrict__ W2, const float* __restrict__ W3) {
    int idx = blockIdx.x * blockDim.x + threadIdx.x;
    const int fTot = GG * NN * 32;
    if (idx < fTot) {
        int g = idx / (NN * 32);
        int r = idx % (NN * 32);
        int n = r / 32, c = r % 32;
        float v = feats[(n * 32 + c) * GG + g];
        __nv_bfloat16 h = __float2bfloat16(v);
        g_Xh[idx] = h;
        g_Xl[idx] = __float2bfloat16(v - __bfloat162float(h));
        return;
    }
    int wi = idx - fTot;
    const int s0 = 256 * 32 * KKN;          // in
    const int s1 = 512 * 256 * KKN;         // r1
    const int s2 = 256 * 512 * KKN;         // r2
    const int s3 = 32 * 256 * KKN;          // out
    const float* W; __nv_bfloat16 *Wh, *Wl; int C, NM, li;
    if (wi < s0)                { W = W0; Wh = g_Bh_in;  Wl = g_Bl_in;  C = 32;  NM = 128; li = wi; }
    else if (wi < s0 + s1)      { W = W1; Wh = g_Bh_r1;  Wl = g_Bl_r1;  C = 256; NM = 128; li = wi - s0; }
    else if (wi < s0 + s1 + s2) { W = W2; Wh = g_Bh_r2;  Wl = g_Bl_r2;  C = 512; NM = 128; li = wi - s0 - s1; }
    else if (wi < s0 + s1 + s2 + s3)
                                { W = W3; Wh = g_Bh_out; Wl = g_Bl_out; C = 256; NM = 32;  li = wi - s0 - s1 - s2; }
    else return;
    const int CK = C * KKN;
    int o = li / CK, ck = li % CK;
    int k = ck / C, c = ck % C;
    float v = W[(o * C + c) * KKN + k];
    __nv_bfloat16 h = __float2bfloat16(v);
    int T = CK / 32, t = ck / 32, j = ck % 32;
    int ob = o / NM, row = o % NM;
    size_t di = ((size_t)(ob * T + t) * NM + row) * 32 + j;
    Wh[di] = h;
    Wl[di] = __float2bfloat16(v - __bfloat162float(h));
}

// ---------------- bf16x3 mma.sync gather-GEMM (pre-split operands) ----------------
// D[n,o] = sum_{k,c} X[nei[g,k]][n][c] * W[o][k*C+c] ; epilogue per flags
template <int C, int O, int NM, bool RELU, bool WF32, bool RRES, bool WSPLIT>
__global__ void __launch_bounds__(256, 2)
k_gemm(const __nv_bfloat16* __restrict__ Ah, const __nv_bfloat16* __restrict__ Al,
       const __nv_bfloat16* __restrict__ Bhg, const __nv_bfloat16* __restrict__ Blg,
       const float* __restrict__ b, const int* __restrict__ nei,
       float* __restrict__ outF,
       const __nv_bfloat16* __restrict__ resH, const __nv_bfloat16* __restrict__ resL,
       __nv_bfloat16* __restrict__ outH, __nv_bfloat16* __restrict__ outL) {
    constexpr int CK  = C * KKN;
    constexpr int T   = CK / 32;
    constexpr int WGN = NM / 32;        // warps along o
    constexpr int WGM = 8 / WGN;        // warps along n
    constexpr int WTM = 128 / WGM;      // warp tile m
    constexpr int MT  = WTM / 16;
    constexpr int NT  = 4;              // warp tile n = 32
    constexpr int AREG = 128 * 64;      // one A matrix region (128 rows x 64B, swizzled)
    constexpr int BREG = NM * 64;
    constexpr int SSZ  = 2 * AREG + 2 * BREG;
    constexpr int S    = 3;             // pipeline stages

    extern __shared__ char smem[];
    __shared__ int   s_nei[KKN];
    __shared__ float s_bias[NM];

    const int tid = threadIdx.x;
    const int g   = blockIdx.z;
    const int n0  = blockIdx.x * 128;
    const int o0  = blockIdx.y * NM;
    const uint32_t sb = smem_u32(smem);

    if (tid < KKN) s_nei[tid] = nei[g * KKN + tid];
    if (tid < NM)  s_bias[tid] = b[o0 + tid];
    __syncthreads();

    const int lane  = tid & 31;
    const int warp  = tid >> 5;
    const int m_off = (warp % WGM) * WTM;
    const int o_off = (warp / WGM) * 32;

    float acc[MT][NT][4];
    #pragma unroll
    for (int mt = 0; mt < MT; mt++)
        #pragma unroll
        for (int nt = 0; nt < NT; nt++)
            #pragma unroll
            for (int q = 0; q < 4; q++) acc[mt][nt][q] = 0.0f;

    auto copyAB = [&](int t, int s) {
        int k = (t * 32) / C, c0 = (t * 32) % C;
        size_t abase = ((size_t)(s_nei[k] * NN + n0)) * C + c0;
        uint32_t as = sb + s * SSZ;
        #pragma unroll
        for (int i = 0; i < 2; i++) {           // 512 16B transfers per A matrix
            int lin = tid + i * 256;
            int row = lin >> 2, seg = lin & 3;
            uint32_t sa = as + swz(row, seg);
            size_t go = abase + (size_t)row * C + seg * 8;
            CP_ASYNC16(sa, Ah + go);
            CP_ASYNC16(sa + AREG, Al + go);
        }
        const __nv_bfloat16* srch = Bhg + (size_t)(blockIdx.y * T + t) * NM * 32;
        const __nv_bfloat16* srcl = Blg + (size_t)(blockIdx.y * T + t) * NM * 32;
        uint32_t bs = sb + s * SSZ + 2 * AREG;
        constexpr int NB = NM * 4;              // 16B transfers per B matrix
        #pragma unroll
        for (int i = 0; i < (NB + 255) / 256; i++) {
            int lin = tid + i * 256;
            if ((NB % 256) && lin >= NB) break;
            int row = lin >> 2, seg = lin & 3;
            uint32_t sa = bs + swz(row, seg);
            CP_ASYNC16(sa, srch + lin * 8);
            CP_ASYNC16(sa + BREG, srcl + lin * 8);
        }
        CP_COMMIT();
    };

    auto compute = [&](int s) {
        uint32_t aB = sb + s * SSZ;
        uint32_t bB = aB + 2 * AREG;
        #pragma unroll
        for (int kh = 0; kh < 2; kh++) {
            uint32_t ah[MT][4], al[MT][4];
            uint32_t bh[NT][2], bl[NT][2];
            #pragma unroll
            for (int mt = 0; mt < MT; mt++) {
                int row = m_off + mt * 16 + (lane & 15);
                uint32_t ad = aB + swz(row, kh * 2 + (lane >> 4));
                ldsm4(ad, ah[mt]);
                ldsm4(ad + AREG, al[mt]);
            }
            #pragma unroll
            for (int p = 0; p < 2; p++) {
                int row = o_off + p * 16 + ((lane >> 4) & 1) * 8 + (lane & 7);
                uint32_t bd = bB + swz(row, kh * 2 + ((lane >> 3) & 1));
                uint32_t r[4];
                ldsm4(bd, r);
                bh[p * 2][0] = r[0]; bh[p * 2][1] = r[1];
                bh[p * 2 + 1][0] = r[2]; bh[p * 2 + 1][1] = r[3];
                ldsm4(bd + BREG, r);
                bl[p * 2][0] = r[0]; bl[p * 2][1] = r[1];
                bl[p * 2 + 1][0] = r[2]; bl[p * 2 + 1][1] = r[3];
            }
            // term-major: same-accumulator reuse distance = MT*NT mmas
            #pragma unroll
            for (int mt = 0; mt < MT; mt++)
                #pragma unroll
                for (int nt = 0; nt < NT; nt++) mma_bf(acc[mt][nt], ah[mt], bh[nt]);
            #pragma unroll
            for (int mt = 0; mt < MT; mt++)
                #pragma unroll
                for (int nt = 0; nt < NT; nt++) mma_bf(acc[mt][nt], al[mt], bh[nt]);
            #pragma unroll
            for (int mt = 0; mt < MT; mt++)
                #pragma unroll
                for (int nt = 0; nt < NT; nt++) mma_bf(acc[mt][nt], ah[mt], bl[nt]);
        }
    };

    // 3-stage cp.async pipeline, one __syncthreads per chunk.
    // At iter t: wait_group 1 -> copy(t) landed (copy(t+1) may be in flight);
    // sync publishes stage t%3 and proves compute(t-1) (stage (t+2)%3) done.
    copyAB(0, 0);
    if (T > 1) copyAB(1, 1);
    for (int t = 0; t < T; t++) {
        int s = t % S;
        if (t + 1 < T) { CP_WAIT1(); } else { CP_WAIT0(); }
        __syncthreads();
        if (t + 2 < T) copyAB(t + 2, (t + 2) % S);
        compute(s);
    }

    // epilogue (acc regs only)
    #pragma unroll
    for (int mt = 0; mt < MT; mt++) {
        int r0 = n0 + m_off + mt * 16 + (lane >> 2);
        #pragma unroll
        for (int nt = 0; nt < NT; nt++) {
            int cl = o_off + nt * 8 + (lane & 3) * 2;
            float b0v = s_bias[cl], b1v = s_bias[cl + 1];
            #pragma unroll
            for (int q = 0; q < 2; q++) {
                int r = r0 + q * 8;
                float vx = acc[mt][nt][q * 2 + 0] + b0v;
                float vy = acc[mt][nt][q * 2 + 1] + b1v;
                if (RELU) { vx = fmaxf(vx, 0.f); vy = fmaxf(vy, 0.f); }
                size_t ei = ((size_t)g * NN + r) * O + o0 + cl;
                if (RRES) {
                    __nv_bfloat162 ph = *(const __nv_bfloat162*)(resH + ei);
                    __nv_bfloat162 pl = *(const __nv_bfloat162*)(resL + ei);
                    vx += __bfloat162float(ph.x) + __bfloat162float(pl.x);
                    vy += __bfloat162float(ph.y) + __bfloat162float(pl.y);
                }
                if (WF32) *(float2*)(outF + ei) = make_float2(vx, vy);
                if (WSPLIT) {
                    float hx = __bfloat162float(__float2bfloat16(vx));
                    float hy = __bfloat162float(__float2bfloat16(vy));
                    *(uint32_t*)(outH + ei) = pk2(hx, hy);
                    *(uint32_t*)(outL + ei) = pk2(vx - hx, vy - hy);
                }
            }
        }
    }
}

// ---------------- epilogue: residual + mean + norms + output ----------------
// out layout: [ feats_inv (N*32) | feats_eqv (N*32*G) ]
__global__ void k_final(const float* __restrict__ feats, float* __restrict__ out) {
    const int n   = blockIdx.x;
    const int tid = threadIdx.x;   // 256 threads
    __shared__ float s_eqv[32][GG];
    __shared__ float s_inv[32];
    __shared__ float s_ng[GG];
    __shared__ float s_ninv;

    for (int idx = tid; idx < 32 * GG; idx += 256) {
        int c = idx / GG;
        int g = idx % GG;
        s_eqv[c][g] = g_E[((size_t)g * NN + n) * 32 + c] + feats[(n * 32 + c) * GG + g];
    }
    __syncthreads();

    if (tid < 32) {
        float sum = 0.0f;
        #pragma unroll 4
        for (int g = 0; g < GG; g++) sum += s_eqv[tid][g];
        s_inv[tid] = sum * (1.0f / GG);
    }
    if (tid >= 64 && tid < 64 + GG) {
        int g = tid - 64;
        float q = 0.0f;
        #pragma unroll
        for (int c = 0; c < 32; c++) { float v = s_eqv[c][g]; q += v * v; }
        s_ng[g] = fmaxf(sqrtf(q), 1e-4f);
    }
    __syncthreads();
    if (tid == 0) {
        float q = 0.0f;
        #pragma unroll
        for (int c = 0; c < 32; c++) q += s_inv[c] * s_inv[c];
        s_ninv = fmaxf(sqrtf(q), 1e-4f);
    }
    __syncthreads();

    if (tid < 32) out[n * 32 + tid] = s_inv[tid] / s_ninv;
    for (int idx = tid; idx < 32 * GG; idx += 256) {
        int c = idx / GG;
        int g = idx % GG;
        out[NN * 32 + (n * 32 + c) * GG + g] = s_eqv[c][g] / s_ng[g];
    }
}

// ---------------- launch (single stream, linear graph) ----------------
extern "C" void kernel_launch(void* const* d_in, const int* in_sizes, int n_in,
                              void* d_out, int out_size) {
    const float* feats = (const float*)d_in[0];
    const int*   nei   = (const int*)  d_in[1];
    const float* W_in  = (const float*)d_in[2];
    const float* b_in  = (const float*)d_in[3];
    const float* W_r1  = (const float*)d_in[4];
    const float* b_r1  = (const float*)d_in[5];
    const float* W_r2  = (const float*)d_in[6];
    const float* b_r2  = (const float*)d_in[7];
    const float* W_out = (const float*)d_in[8];
    const float* b_out = (const float*)d_in[9];
    float* out = (float*)d_out;

    void *pE, *pXh, *pXl, *pHh, *pHl, *pRh, *pRl;
    void *pBh_in, *pBl_in, *pBh_r1, *pBl_r1, *pBh_r2, *pBl_r2, *pBh_out, *pBl_out;
    cudaGetSymbolAddress(&pE,  g_E);
    cudaGetSymbolAddress(&pXh, g_Xh);  cudaGetSymbolAddress(&pXl, g_Xl);
    cudaGetSymbolAddress(&pHh, g_Hh);  cudaGetSymbolAddress(&pHl, g_Hl);
    cudaGetSymbolAddress(&pRh, g_Rh);  cudaGetSymbolAddress(&pRl, g_Rl);
    cudaGetSymbolAddress(&pBh_in,  g_Bh_in);   cudaGetSymbolAddress(&pBl_in,  g_Bl_in);
    cudaGetSymbolAddress(&pBh_r1,  g_Bh_r1);   cudaGetSymbolAddress(&pBl_r1,  g_Bl_r1);
    cudaGetSymbolAddress(&pBh_r2,  g_Bh_r2);   cudaGetSymbolAddress(&pBl_r2,  g_Bl_r2);
    cudaGetSymbolAddress(&pBh_out, g_Bh_out);  cudaGetSymbolAddress(&pBl_out, g_Bl_out);

    const int SM128 = 3 * (2 * 128 * 64 + 2 * 128 * 64);   // 98304
    const int SM32  = 3 * (2 * 128 * 64 + 2 * 32 * 64);    // 61440
    cudaFuncSetAttribute((const void*)k_gemm<32, 256, 128, false, false, false, true>,
                         cudaFuncAttributeMaxDynamicSharedMemorySize, SM128);
    cudaFuncSetAttribute((const void*)k_gemm<256, 512, 128, true, false, false, true>,
                         cudaFuncAttributeMaxDynamicSharedMemorySize, SM128);
    cudaFuncSetAttribute((const void*)k_gemm<512, 256, 128, false, false, true, true>,
                         cudaFuncAttributeMaxDynamicSharedMemorySize, SM128);
    cudaFuncSetAttribute((const void*)k_gemm<256, 32, 32, false, true, false, false>,
                         cudaFuncAttributeMaxDynamicSharedMemorySize, SM32);

    // 1. fused prep: feats split + all four weight splits (one launch)
    {
        int total = GG * NN * 32
                  + (256 * 32 + 512 * 256 + 256 * 512 + 32 * 256) * KKN;
        k_prep<<<(total + 255) / 256, 256>>>(feats, W_in, W_r1, W_r2, W_out);
    }
    // 2. in: Hh/Hl = split(comb(X, W_in) + b_in)
    k_gemm<32, 256, 128, false, false, false, true><<<dim3(4, 2, GG), 256, SM128>>>(
        (const __nv_bfloat16*)pXh, (const __nv_bfloat16*)pXl,
        (const __nv_bfloat16*)pBh_in, (const __nv_bfloat16*)pBl_in,
        b_in, nei, nullptr, nullptr, nullptr,
        (__nv_bfloat16*)pHh, (__nv_bfloat16*)pHl);
    // 3. r1: Rh/Rl = split(relu(comb(H, W_r1) + b_r1))
    k_gemm<256, 512, 128, true, false, false, true><<<dim3(4, 4, GG), 256, SM128>>>(
        (const __nv_bfloat16*)pHh, (const __nv_bfloat16*)pHl,
        (const __nv_bfloat16*)pBh_r1, (const __nv_bfloat16*)pBl_r1,
        b_r1, nei, nullptr, nullptr, nullptr,
        (__nv_bfloat16*)pRh, (__nv_bfloat16*)pRl);
    // 4. r2: Hh/Hl = split((Hh+Hl) + comb(R, W_r2) + b_r2)   (in-place residual)
    k_gemm<512, 256, 128, false, false, true, true><<<dim3(4, 2, GG), 256, SM128>>>(
        (const __nv_bfloat16*)pRh, (const __nv_bfloat16*)pRl,
        (const __nv_bfloat16*)pBh_r2, (const __nv_bfloat16*)pBl_r2,
        b_r2, nei, nullptr,
        (const __nv_bfloat16*)pHh, (const __nv_bfloat16*)pHl,
        (__nv_bfloat16*)pHh, (__nv_bfloat16*)pHl);
    // 5. out: E = comb(Hnew, W_out) + b_out (fp32)
    k_gemm<256, 32, 32, false, true, false, false><<<dim3(4, 1, GG), 256, SM32>>>(
        (const __nv_bfloat16*)pHh, (const __nv_bfloat16*)pHl,
        (const __nv_bfloat16*)pBh_out, (const __nv_bfloat16*)pBl_out,
        b_out, nei, (float*)pE, nullptr, nullptr, nullptr, nullptr);
    // 6. final: residual + mean + norms
    k_final<<<NN, 256>>>(feats, out);
}

// round 9
// speedup vs baseline: 4.1426x; 1.0524x over previous
#include <cuda_runtime.h>
#include <cuda_bf16.h>
#include <cstdint>

#define NN  512
#define GG  60
#define KKN 13

// ---------------- scratch (device globals; allocation-free) ----------------
__device__ float g_E [GG * NN * 32];                   // conv_out result fp32
// split activations (bf16 hi/lo), layout [g, n, C]
__device__ __nv_bfloat16 g_Xh[GG * NN * 32],            g_Xl[GG * NN * 32];
__device__ __nv_bfloat16 g_Hh[(size_t)GG * NN * 256],   g_Hl[(size_t)GG * NN * 256];
__device__ __nv_bfloat16 g_Rh[(size_t)GG * NN * 512],   g_Rl[(size_t)GG * NN * 512];
// weight chunk images (bf16 hi/lo): [o_blk][chunk t][row o (NM)][32]
__device__ __nv_bfloat16 g_Bh_in [256 * 32  * KKN], g_Bl_in [256 * 32  * KKN];
__device__ __nv_bfloat16 g_Bh_r1 [512 * 256 * KKN], g_Bl_r1 [512 * 256 * KKN];
__device__ __nv_bfloat16 g_Bh_r2 [256 * 512 * KKN], g_Bl_r2 [256 * 512 * KKN];
__device__ __nv_bfloat16 g_Bh_out[32  * 256 * KKN], g_Bl_out[32  * 256 * KKN];

// ---------------- helpers ----------------
__device__ __forceinline__ uint32_t smem_u32(const void* p) {
    uint32_t a;
    asm("{ .reg .u64 t; cvta.to.shared.u64 t, %1; cvt.u32.u64 %0, t; }" : "=r"(a) : "l"(p));
    return a;
}
__device__ __forceinline__ uint32_t pk2(float x, float y) {
    __nv_bfloat162 t = __floats2bfloat162_rn(x, y);
    return *reinterpret_cast<uint32_t*>(&t);
}
// 64B-row swizzle: permute 16B chunk index by (row>>1)&3 -> conflict-free ldmatrix
__device__ __forceinline__ uint32_t swz(int row, int chunk) {
    return (uint32_t)(row * 64 + ((chunk ^ ((row >> 1) & 3)) * 16));
}
__device__ __forceinline__ void ldsm4(uint32_t a, uint32_t r[4]) {
    asm volatile("ldmatrix.sync.aligned.m8n8.x4.shared.b16 {%0,%1,%2,%3}, [%4];"
        : "=r"(r[0]), "=r"(r[1]), "=r"(r[2]), "=r"(r[3]) : "r"(a));
}
__device__ __forceinline__ void mma_bf(float d[4], const uint32_t a[4], const uint32_t b[2]) {
    asm volatile("mma.sync.aligned.m16n8k16.row.col.f32.bf16.bf16.f32 "
        "{%0,%1,%2,%3}, {%4,%5,%6,%7}, {%8,%9}, {%0,%1,%2,%3};"
        : "+f"(d[0]), "+f"(d[1]), "+f"(d[2]), "+f"(d[3])
        : "r"(a[0]), "r"(a[1]), "r"(a[2]), "r"(a[3]), "r"(b[0]), "r"(b[1]));
}
#define CP_ASYNC16(saddr, gptr) \
    asm volatile("cp.async.ca.shared.global [%0], [%1], 16;" :: "r"(saddr), "l"(gptr) : "memory")
#define CP_COMMIT()  asm volatile("cp.async.commit_group;" ::: "memory")
#define CP_WAIT0()   asm volatile("cp.async.wait_group 0;" ::: "memory")

// ---------------- fused prep: feats split + all four weight splits ----------------
__global__ void k_prep(const float* __restrict__ feats,
                       const float* __restrict__ W0, const float* __restrict__ W1,
                       const float* __restrict__ W2, const float* __restrict__ W3) {
    int idx = blockIdx.x * blockDim.x + threadIdx.x;
    const int fTot = GG * NN * 32;
    if (idx < fTot) {
        int g = idx / (NN * 32);
        int r = idx % (NN * 32);
        int n = r / 32, c = r % 32;
        float v = feats[(n * 32 + c) * GG + g];
        __nv_bfloat16 h = __float2bfloat16(v);
        g_Xh[idx] = h;
        g_Xl[idx] = __float2bfloat16(v - __bfloat162float(h));
        return;
    }
    int wi = idx - fTot;
    const int s0 = 256 * 32 * KKN;          // in
    const int s1 = 512 * 256 * KKN;         // r1
    const int s2 = 256 * 512 * KKN;         // r2
    const int s3 = 32 * 256 * KKN;          // out
    const float* W; __nv_bfloat16 *Wh, *Wl; int C, NM, li;
    if (wi < s0)                { W = W0; Wh = g_Bh_in;  Wl = g_Bl_in;  C = 32;  NM = 128; li = wi; }
    else if (wi < s0 + s1)      { W = W1; Wh = g_Bh_r1;  Wl = g_Bl_r1;  C = 256; NM = 128; li = wi - s0; }
    else if (wi < s0 + s1 + s2) { W = W2; Wh = g_Bh_r2;  Wl = g_Bl_r2;  C = 512; NM = 128; li = wi - s0 - s1; }
    else if (wi < s0 + s1 + s2 + s3)
                                { W = W3; Wh = g_Bh_out; Wl = g_Bl_out; C = 256; NM = 32;  li = wi - s0 - s1 - s2; }
    else return;
    const int CK = C * KKN;
    int o = li / CK, ck = li % CK;
    int k = ck / C, c = ck % C;
    float v = W[(o * C + c) * KKN + k];
    __nv_bfloat16 h = __float2bfloat16(v);
    int T = CK / 32, t = ck / 32, j = ck % 32;
    int ob = o / NM, row = o % NM;
    size_t di = ((size_t)(ob * T + t) * NM + row) * 32 + j;
    Wh[di] = h;
    Wl[di] = __float2bfloat16(v - __bfloat162float(h));
}

// ---------------- bf16x3 mma.sync gather-GEMM (pre-split operands) ----------------
// D[n,o] = sum_{k,c} X[nei[g,k]][n][c] * W[o][k*C+c] ; epilogue per flags
// CTA tile: MTILE x NM. 8 warps. 2-stage cp.async pipeline, 1 sync/chunk.
template <int C, int O, int MTILE, int NM, bool RELU, bool WF32, bool RRES, bool WSPLIT>
__global__ void __launch_bounds__(256, 3)
k_gemm(const __nv_bfloat16* __restrict__ Ah, const __nv_bfloat16* __restrict__ Al,
       const __nv_bfloat16* __restrict__ Bhg, const __nv_bfloat16* __restrict__ Blg,
       const float* __restrict__ b, const int* __restrict__ nei,
       float* __restrict__ outF,
       const __nv_bfloat16* __restrict__ resH, const __nv_bfloat16* __restrict__ resL,
       __nv_bfloat16* __restrict__ outH, __nv_bfloat16* __restrict__ outL) {
    constexpr int CK  = C * KKN;
    constexpr int T   = CK / 32;
    constexpr int WGN = NM / 32;        // warps along o
    constexpr int WGM = 8 / WGN;        // warps along n
    constexpr int WTM = MTILE / WGM;    // warp tile m
    constexpr int MT  = WTM / 16;
    static_assert(WTM >= 16, "warp tile too small");
    constexpr int NT  = 4;              // warp tile n = 32
    constexpr int AREG = MTILE * 64;    // one A matrix region (MTILE rows x 64B, swizzled)
    constexpr int BREG = NM * 64;
    constexpr int SSZ  = 2 * AREG + 2 * BREG;

    extern __shared__ char smem[];
    __shared__ int   s_nei[KKN];
    __shared__ float s_bias[NM];

    const int tid = threadIdx.x;
    const int g   = blockIdx.z;
    const int n0  = blockIdx.x * MTILE;
    const int o0  = blockIdx.y * NM;
    const uint32_t sb = smem_u32(smem);

    if (tid < KKN) s_nei[tid] = nei[g * KKN + tid];
    if (tid < NM)  s_bias[tid] = b[o0 + tid];
    __syncthreads();

    const int lane  = tid & 31;
    const int warp  = tid >> 5;
    const int m_off = (warp % WGM) * WTM;
    const int o_off = (warp / WGM) * 32;

    float acc[MT][NT][4];
    #pragma unroll
    for (int mt = 0; mt < MT; mt++)
        #pragma unroll
        for (int nt = 0; nt < NT; nt++)
            #pragma unroll
            for (int q = 0; q < 4; q++) acc[mt][nt][q] = 0.0f;

    auto copyAB = [&](int t, int s) {
        int k = (t * 32) / C, c0 = (t * 32) % C;
        size_t abase = ((size_t)(s_nei[k] * NN + n0)) * C + c0;
        uint32_t as = sb + s * SSZ;
        constexpr int NA = MTILE * 4;           // 16B transfers per A matrix
        #pragma unroll
        for (int i = 0; i < (NA + 255) / 256; i++) {
            int lin = tid + i * 256;
            if ((NA % 256) && lin >= NA) break;
            int row = lin >> 2, seg = lin & 3;
            uint32_t sa = as + swz(row, seg);
            size_t go = abase + (size_t)row * C + seg * 8;
            CP_ASYNC16(sa, Ah + go);
            CP_ASYNC16(sa + AREG, Al + go);
        }
        const __nv_bfloat16* srch = Bhg + (size_t)(blockIdx.y * T + t) * NM * 32;
        const __nv_bfloat16* srcl = Blg + (size_t)(blockIdx.y * T + t) * NM * 32;
        uint32_t bs = sb + s * SSZ + 2 * AREG;
        constexpr int NB = NM * 4;              // 16B transfers per B matrix
        #pragma unroll
        for (int i = 0; i < (NB + 255) / 256; i++) {
            int lin = tid + i * 256;
            if ((NB % 256) && lin >= NB) break;
            int row = lin >> 2, seg = lin & 3;
            uint32_t sa = bs + swz(row, seg);
            CP_ASYNC16(sa, srch + lin * 8);
            CP_ASYNC16(sa + BREG, srcl + lin * 8);
        }
        CP_COMMIT();
    };

    auto compute = [&](int s) {
        uint32_t aB = sb + s * SSZ;
        uint32_t bB = aB + 2 * AREG;
        #pragma unroll
        for (int kh = 0; kh < 2; kh++) {
            uint32_t ah[MT][4], al[MT][4];
            uint32_t bh[NT][2], bl[NT][2];
            #pragma unroll
            for (int mt = 0; mt < MT; mt++) {
                int row = m_off + mt * 16 + (lane & 15);
                uint32_t ad = aB + swz(row, kh * 2 + (lane >> 4));
                ldsm4(ad, ah[mt]);
                ldsm4(ad + AREG, al[mt]);
            }
            #pragma unroll
            for (int p = 0; p < 2; p++) {
                int row = o_off + p * 16 + ((lane >> 4) & 1) * 8 + (lane & 7);
                uint32_t bd = bB + swz(row, kh * 2 + ((lane >> 3) & 1));
                uint32_t r[4];
                ldsm4(bd, r);
                bh[p * 2][0] = r[0]; bh[p * 2][1] = r[1];
                bh[p * 2 + 1][0] = r[2]; bh[p * 2 + 1][1] = r[3];
                ldsm4(bd + BREG, r);
                bl[p * 2][0] = r[0]; bl[p * 2][1] = r[1];
                bl[p * 2 + 1][0] = r[2]; bl[p * 2 + 1][1] = r[3];
            }
            // term-major: same-accumulator reuse distance = MT*NT mmas
            #pragma unroll
            for (int mt = 0; mt < MT; mt++)
                #pragma unroll
                for (int nt = 0; nt < NT; nt++) mma_bf(acc[mt][nt], ah[mt], bh[nt]);
            #pragma unroll
            for (int mt = 0; mt < MT; mt++)
                #pragma unroll
                for (int nt = 0; nt < NT; nt++) mma_bf(acc[mt][nt], al[mt], bh[nt]);
            #pragma unroll
            for (int mt = 0; mt < MT; mt++)
                #pragma unroll
                for (int nt = 0; nt < NT; nt++) mma_bf(acc[mt][nt], ah[mt], bl[nt]);
        }
    };

    // 2-stage cp.async pipeline, one __syncthreads per chunk:
    //   wait(copy t) -> sync (publishes stage s; proves stage s^1 compute done)
    //   -> issue copy(t+1) into s^1 -> compute(s)
    copyAB(0, 0);
    for (int t = 0; t < T; t++) {
        int s = t & 1;
        CP_WAIT0();
        __syncthreads();
        if (t + 1 < T) copyAB(t + 1, s ^ 1);
        compute(s);
    }

    // epilogue (acc regs only)
    #pragma unroll
    for (int mt = 0; mt < MT; mt++) {
        int r0 = n0 + m_off + mt * 16 + (lane >> 2);
        #pragma unroll
        for (int nt = 0; nt < NT; nt++) {
            int cl = o_off + nt * 8 + (lane & 3) * 2;
            float b0v = s_bias[cl], b1v = s_bias[cl + 1];
            #pragma unroll
            for (int q = 0; q < 2; q++) {
                int r = r0 + q * 8;
                float vx = acc[mt][nt][q * 2 + 0] + b0v;
                float vy = acc[mt][nt][q * 2 + 1] + b1v;
                if (RELU) { vx = fmaxf(vx, 0.f); vy = fmaxf(vy, 0.f); }
                size_t ei = ((size_t)g * NN + r) * O + o0 + cl;
                if (RRES) {
                    __nv_bfloat162 ph = *(const __nv_bfloat162*)(resH + ei);
                    __nv_bfloat162 pl = *(const __nv_bfloat162*)(resL + ei);
                    vx += __bfloat162float(ph.x) + __bfloat162float(pl.x);
                    vy += __bfloat162float(ph.y) + __bfloat162float(pl.y);
                }
                if (WF32) *(float2*)(outF + ei) = make_float2(vx, vy);
                if (WSPLIT) {
                    float hx = __bfloat162float(__float2bfloat16(vx));
                    float hy = __bfloat162float(__float2bfloat16(vy));
                    *(uint32_t*)(outH + ei) = pk2(hx, hy);
                    *(uint32_t*)(outL + ei) = pk2(vx - hx, vy - hy);
                }
            }
        }
    }
}

// ---------------- epilogue: residual + mean + norms + output ----------------
// out layout: [ feats_inv (N*32) | feats_eqv (N*32*G) ]
__global__ void k_final(const float* __restrict__ feats, float* __restrict__ out) {
    const int n   = blockIdx.x;
    const int tid = threadIdx.x;   // 256 threads
    __shared__ float s_eqv[32][GG];
    __shared__ float s_inv[32];
    __shared__ float s_ng[GG];
    __shared__ float s_ninv;

    for (int idx = tid; idx < 32 * GG; idx += 256) {
        int c = idx / GG;
        int g = idx % GG;
        s_eqv[c][g] = g_E[((size_t)g * NN + n) * 32 + c] + feats[(n * 32 + c) * GG + g];
    }
    __syncthreads();

    if (tid < 32) {
        float sum = 0.0f;
        #pragma unroll 4
        for (int g = 0; g < GG; g++) sum += s_eqv[tid][g];
        s_inv[tid] = sum * (1.0f / GG);
    }
    if (tid >= 64 && tid < 64 + GG) {
        int g = tid - 64;
        float q = 0.0f;
        #pragma unroll
        for (int c = 0; c < 32; c++) { float v = s_eqv[c][g]; q += v * v; }
        s_ng[g] = fmaxf(sqrtf(q), 1e-4f);
    }
    __syncthreads();
    if (tid == 0) {
        float q = 0.0f;
        #pragma unroll
        for (int c = 0; c < 32; c++) q += s_inv[c] * s_inv[c];
        s_ninv = fmaxf(sqrtf(q), 1e-4f);
    }
    __syncthreads();

    if (tid < 32) out[n * 32 + tid] = s_inv[tid] / s_ninv;
    for (int idx = tid; idx < 32 * GG; idx += 256) {
        int c = idx / GG;
        int g = idx % GG;
        out[NN * 32 + (n * 32 + c) * GG + g] = s_eqv[c][g] / s_ng[g];
    }
}

// ---------------- launch (single stream, linear graph) ----------------
extern "C" void kernel_launch(void* const* d_in, const int* in_sizes, int n_in,
                              void* d_out, int out_size) {
    const float* feats = (const float*)d_in[0];
    const int*   nei   = (const int*)  d_in[1];
    const float* W_in  = (const float*)d_in[2];
    const float* b_in  = (const float*)d_in[3];
    const float* W_r1  = (const float*)d_in[4];
    const float* b_r1  = (const float*)d_in[5];
    const float* W_r2  = (const float*)d_in[6];
    const float* b_r2  = (const float*)d_in[7];
    const float* W_out = (const float*)d_in[8];
    const float* b_out = (const float*)d_in[9];
    float* out = (float*)d_out;

    void *pE, *pXh, *pXl, *pHh, *pHl, *pRh, *pRl;
    void *pBh_in, *pBl_in, *pBh_r1, *pBl_r1, *pBh_r2, *pBl_r2, *pBh_out, *pBl_out;
    cudaGetSymbolAddress(&pE,  g_E);
    cudaGetSymbolAddress(&pXh, g_Xh);  cudaGetSymbolAddress(&pXl, g_Xl);
    cudaGetSymbolAddress(&pHh, g_Hh);  cudaGetSymbolAddress(&pHl, g_Hl);
    cudaGetSymbolAddress(&pRh, g_Rh);  cudaGetSymbolAddress(&pRl, g_Rl);
    cudaGetSymbolAddress(&pBh_in,  g_Bh_in);   cudaGetSymbolAddress(&pBl_in,  g_Bl_in);
    cudaGetSymbolAddress(&pBh_r1,  g_Bh_r1);   cudaGetSymbolAddress(&pBl_r1,  g_Bl_r1);
    cudaGetSymbolAddress(&pBh_r2,  g_Bh_r2);   cudaGetSymbolAddress(&pBl_r2,  g_Bl_r2);
    cudaGetSymbolAddress(&pBh_out, g_Bh_out);  cudaGetSymbolAddress(&pBl_out, g_Bl_out);

    const int SMA = 2 * (2 * 64 * 64 + 2 * 128 * 64);   // 49152 (64x128 tiles)
    const int SMO = 2 * (2 * 128 * 64 + 2 * 32 * 64);   // 40960 (128x32 tile)
    cudaFuncSetAttribute((const void*)k_gemm<32, 256, 64, 128, false, false, false, true>,
                         cudaFuncAttributeMaxDynamicSharedMemorySize, SMA);
    cudaFuncSetAttribute((const void*)k_gemm<256, 512, 64, 128, true, false, false, true>,
                         cudaFuncAttributeMaxDynamicSharedMemorySize, SMA);
    cudaFuncSetAttribute((const void*)k_gemm<512, 256, 64, 128, false, false, true, true>,
                         cudaFuncAttributeMaxDynamicSharedMemorySize, SMA);
    cudaFuncSetAttribute((const void*)k_gemm<256, 32, 128, 32, false, true, false, false>,
                         cudaFuncAttributeMaxDynamicSharedMemorySize, SMO);

    // 1. fused prep: feats split + all four weight splits (one launch)
    {
        int total = GG * NN * 32
                  + (256 * 32 + 512 * 256 + 256 * 512 + 32 * 256) * KKN;
        k_prep<<<(total + 255) / 256, 256>>>(feats, W_in, W_r1, W_r2, W_out);
    }
    // 2. in: Hh/Hl = split(comb(X, W_in) + b_in)
    k_gemm<32, 256, 64, 128, false, false, false, true><<<dim3(8, 2, GG), 256, SMA>>>(
        (const __nv_bfloat16*)pXh, (const __nv_bfloat16*)pXl,
        (const __nv_bfloat16*)pBh_in, (const __nv_bfloat16*)pBl_in,
        b_in, nei, nullptr, nullptr, nullptr,
        (__nv_bfloat16*)pHh, (__nv_bfloat16*)pHl);
    // 3. r1: Rh/Rl = split(relu(comb(H, W_r1) + b_r1))
    k_gemm<256, 512, 64, 128, true, false, false, true><<<dim3(8, 4, GG), 256, SMA>>>(
        (const __nv_bfloat16*)pHh, (const __nv_bfloat16*)pHl,
        (const __nv_bfloat16*)pBh_r1, (const __nv_bfloat16*)pBl_r1,
        b_r1, nei, nullptr, nullptr, nullptr,
        (__nv_bfloat16*)pRh, (__nv_bfloat16*)pRl);
    // 4. r2: Hh/Hl = split((Hh+Hl) + comb(R, W_r2) + b_r2)   (in-place residual)
    k_gemm<512, 256, 64, 128, false, false, true, true><<<dim3(8, 2, GG), 256, SMA>>>(
        (const __nv_bfloat16*)pRh, (const __nv_bfloat16*)pRl,
        (const __nv_bfloat16*)pBh_r2, (const __nv_bfloat16*)pBl_r2,
        b_r2, nei, nullptr,
        (const __nv_bfloat16*)pHh, (const __nv_bfloat16*)pHl,
        (__nv_bfloat16*)pHh, (__nv_bfloat16*)pHl);
    // 5. out: E = comb(Hnew, W_out) + b_out (fp32)
    k_gemm<256, 32, 128, 32, false, true, false, false><<<dim3(4, 1, GG), 256, SMO>>>(
        (const __nv_bfloat16*)pHh, (const __nv_bfloat16*)pHl,
        (const __nv_bfloat16*)pBh_out, (const __nv_bfloat16*)pBl_out,
        b_out, nei, (float*)pE, nullptr, nullptr, nullptr, nullptr);
    // 6. final: residual + mean + norms
    k_final<<<NN, 256>>>(feats, out);
}

// round 10
// speedup vs baseline: 4.9391x; 1.1923x over previous
#include <cuda_runtime.h>
#include <cuda_bf16.h>
#include <cstdint>

#define NN  512
#define GG  60
#define KKN 13

// ---------------- scratch (device globals; allocation-free) ----------------
__device__ float g_E [GG * NN * 32];                   // conv_out result fp32
// split activations (bf16 hi/lo), layout [g, n, C]
__device__ __nv_bfloat16 g_Xh[GG * NN * 32],            g_Xl[GG * NN * 32];
__device__ __nv_bfloat16 g_Hh[(size_t)GG * NN * 256],   g_Hl[(size_t)GG * NN * 256];
__device__ __nv_bfloat16 g_Rh[(size_t)GG * NN * 512],   g_Rl[(size_t)GG * NN * 512];
// weight chunk images (bf16 hi/lo): [o_blk][chunk t][row o (NM)][32]
__device__ __nv_bfloat16 g_Bh_in [256 * 32  * KKN], g_Bl_in [256 * 32  * KKN];
__device__ __nv_bfloat16 g_Bh_r1 [512 * 256 * KKN], g_Bl_r1 [512 * 256 * KKN];
__device__ __nv_bfloat16 g_Bh_r2 [256 * 512 * KKN], g_Bl_r2 [256 * 512 * KKN];
__device__ __nv_bfloat16 g_Bh_out[32  * 256 * KKN], g_Bl_out[32  * 256 * KKN];

// ---------------- helpers ----------------
__device__ __forceinline__ uint32_t smem_u32(const void* p) {
    uint32_t a;
    asm("{ .reg .u64 t; cvta.to.shared.u64 t, %1; cvt.u32.u64 %0, t; }" : "=r"(a) : "l"(p));
    return a;
}
__device__ __forceinline__ uint32_t pk2(float x, float y) {
    __nv_bfloat162 t = __floats2bfloat162_rn(x, y);
    return *reinterpret_cast<uint32_t*>(&t);
}
// 64B-row swizzle: permute 16B chunk index by (row>>1)&3 -> conflict-free ldmatrix
__device__ __forceinline__ uint32_t swz(int row, int chunk) {
    return (uint32_t)(row * 64 + ((chunk ^ ((row >> 1) & 3)) * 16));
}
__device__ __forceinline__ void ldsm4(uint32_t a, uint32_t r[4]) {
    asm volatile("ldmatrix.sync.aligned.m8n8.x4.shared.b16 {%0,%1,%2,%3}, [%4];"
        : "=r"(r[0]), "=r"(r[1]), "=r"(r[2]), "=r"(r[3]) : "r"(a));
}
__device__ __forceinline__ void mma_bf(float d[4], const uint32_t a[4], const uint32_t b[2]) {
    asm volatile("mma.sync.aligned.m16n8k16.row.col.f32.bf16.bf16.f32 "
        "{%0,%1,%2,%3}, {%4,%5,%6,%7}, {%8,%9}, {%0,%1,%2,%3};"
        : "+f"(d[0]), "+f"(d[1]), "+f"(d[2]), "+f"(d[3])
        : "r"(a[0]), "r"(a[1]), "r"(a[2]), "r"(a[3]), "r"(b[0]), "r"(b[1]));
}
#define CP_ASYNC16(saddr, gptr) \
    asm volatile("cp.async.cg.shared.global [%0], [%1], 16;" :: "r"(saddr), "l"(gptr) : "memory")
#define CP_COMMIT()  asm volatile("cp.async.commit_group;" ::: "memory")
#define CP_WAIT0()   asm volatile("cp.async.wait_group 0;" ::: "memory")

// ---------------- fused prep: feats split + all four weight splits ----------------
__global__ void k_prep(const float* __restrict__ feats,
                       const float* __restrict__ W0, const float* __restrict__ W1,
                       const float* __restrict__ W2, const float* __restrict__ W3) {
    int idx = blockIdx.x * blockDim.x + threadIdx.x;
    const int fTot = GG * NN * 32;
    if (idx < fTot) {
        int g = idx / (NN * 32);
        int r = idx % (NN * 32);
        int n = r / 32, c = r % 32;
        float v = feats[(n * 32 + c) * GG + g];
        __nv_bfloat16 h = __float2bfloat16(v);
        g_Xh[idx] = h;
        g_Xl[idx] = __float2bfloat16(v - __bfloat162float(h));
        return;
    }
    int wi = idx - fTot;
    const int s0 = 256 * 32 * KKN;          // in
    const int s1 = 512 * 256 * KKN;         // r1
    const int s2 = 256 * 512 * KKN;         // r2
    const int s3 = 32 * 256 * KKN;          // out
    const float* W; __nv_bfloat16 *Wh, *Wl; int C, NM, li;
    if (wi < s0)                { W = W0; Wh = g_Bh_in;  Wl = g_Bl_in;  C = 32;  NM = 128; li = wi; }
    else if (wi < s0 + s1)      { W = W1; Wh = g_Bh_r1;  Wl = g_Bl_r1;  C = 256; NM = 128; li = wi - s0; }
    else if (wi < s0 + s1 + s2) { W = W2; Wh = g_Bh_r2;  Wl = g_Bl_r2;  C = 512; NM = 128; li = wi - s0 - s1; }
    else if (wi < s0 + s1 + s2 + s3)
                                { W = W3; Wh = g_Bh_out; Wl = g_Bl_out; C = 256; NM = 32;  li = wi - s0 - s1 - s2; }
    else return;
    const int CK = C * KKN;
    int o = li / CK, ck = li % CK;
    int k = ck / C, c = ck % C;
    float v = W[(o * C + c) * KKN + k];
    __nv_bfloat16 h = __float2bfloat16(v);
    int T = CK / 32, t = ck / 32, j = ck % 32;
    int ob = o / NM, row = o % NM;
    size_t di = ((size_t)(ob * T + t) * NM + row) * 32 + j;
    Wh[di] = h;
    Wl[di] = __float2bfloat16(v - __bfloat162float(h));
}

// ---------------- bf16x3 mma.sync gather-GEMM (pre-split operands) ----------------
// D[n,o] = sum_{k,c} X[nei[g,k]][n][c] * W[o][k*C+c] ; epilogue per flags
// CTA tile: MTILE x NM, 4 warps (128 threads), 4 CTAs/SM.
// 2-stage cp.async pipeline, 1 sync/chunk.
template <int C, int O, int MTILE, int NM, bool RELU, bool WF32, bool RRES, bool WSPLIT>
__global__ void __launch_bounds__(128, 4)
k_gemm(const __nv_bfloat16* __restrict__ Ah, const __nv_bfloat16* __restrict__ Al,
       const __nv_bfloat16* __restrict__ Bhg, const __nv_bfloat16* __restrict__ Blg,
       const float* __restrict__ b, const int* __restrict__ nei,
       float* __restrict__ outF,
       const __nv_bfloat16* __restrict__ resH, const __nv_bfloat16* __restrict__ resL,
       __nv_bfloat16* __restrict__ outH, __nv_bfloat16* __restrict__ outL) {
    constexpr int NTHR = 128;
    constexpr int NWARP = 4;
    constexpr int CK  = C * KKN;
    constexpr int T   = CK / 32;
    constexpr int WGN = (NM / 32 < NWARP) ? NM / 32 : NWARP;   // warps along o
    constexpr int WGM = NWARP / WGN;    // warps along n
    constexpr int WTM = MTILE / WGM;    // warp tile m
    constexpr int MT  = WTM / 16;
    static_assert(WTM >= 16, "warp tile too small");
    constexpr int NT  = 4;              // warp tile n = 32
    constexpr int AREG = MTILE * 64;    // one A matrix region (MTILE rows x 64B, swizzled)
    constexpr int BREG = NM * 64;
    constexpr int SSZ  = 2 * AREG + 2 * BREG;

    extern __shared__ char smem[];
    __shared__ int   s_nei[KKN];
    __shared__ float s_bias[NM];

    const int tid = threadIdx.x;
    const int g   = blockIdx.z;
    const int n0  = blockIdx.x * MTILE;
    const int o0  = blockIdx.y * NM;
    const uint32_t sb = smem_u32(smem);

    if (tid < KKN) s_nei[tid] = nei[g * KKN + tid];
    for (int i = tid; i < NM; i += NTHR) s_bias[i] = b[o0 + i];
    __syncthreads();

    const int lane  = tid & 31;
    const int warp  = tid >> 5;
    const int m_off = (warp % WGM) * WTM;
    const int o_off = (warp / WGM) * 32;

    float acc[MT][NT][4];
    #pragma unroll
    for (int mt = 0; mt < MT; mt++)
        #pragma unroll
        for (int nt = 0; nt < NT; nt++)
            #pragma unroll
            for (int q = 0; q < 4; q++) acc[mt][nt][q] = 0.0f;

    auto copyAB = [&](int t, int s) {
        int k = (t * 32) / C, c0 = (t * 32) % C;
        size_t abase = ((size_t)(s_nei[k] * NN + n0)) * C + c0;
        uint32_t as = sb + s * SSZ;
        constexpr int NA = MTILE * 4;           // 16B transfers per A matrix
        #pragma unroll
        for (int i = 0; i < (NA + NTHR - 1) / NTHR; i++) {
            int lin = tid + i * NTHR;
            if ((NA % NTHR) && lin >= NA) break;
            int row = lin >> 2, seg = lin & 3;
            uint32_t sa = as + swz(row, seg);
            size_t go = abase + (size_t)row * C + seg * 8;
            CP_ASYNC16(sa, Ah + go);
            CP_ASYNC16(sa + AREG, Al + go);
        }
        const __nv_bfloat16* srch = Bhg + (size_t)(blockIdx.y * T + t) * NM * 32;
        const __nv_bfloat16* srcl = Blg + (size_t)(blockIdx.y * T + t) * NM * 32;
        uint32_t bs = sb + s * SSZ + 2 * AREG;
        constexpr int NB = NM * 4;              // 16B transfers per B matrix
        #pragma unroll
        for (int i = 0; i < (NB + NTHR - 1) / NTHR; i++) {
            int lin = tid + i * NTHR;
            if ((NB % NTHR) && lin >= NB) break;
            int row = lin >> 2, seg = lin & 3;
            uint32_t sa = bs + swz(row, seg);
            CP_ASYNC16(sa, srch + lin * 8);
            CP_ASYNC16(sa + BREG, srcl + lin * 8);
        }
        CP_COMMIT();
    };

    auto compute = [&](int s) {
        uint32_t aB = sb + s * SSZ;
        uint32_t bB = aB + 2 * AREG;
        #pragma unroll
        for (int kh = 0; kh < 2; kh++) {
            uint32_t ah[MT][4], al[MT][4];
            uint32_t bh[NT][2], bl[NT][2];
            #pragma unroll
            for (int mt = 0; mt < MT; mt++) {
                int row = m_off + mt * 16 + (lane & 15);
                uint32_t ad = aB + swz(row, kh * 2 + (lane >> 4));
                ldsm4(ad, ah[mt]);
                ldsm4(ad + AREG, al[mt]);
            }
            #pragma unroll
            for (int p = 0; p < 2; p++) {
                int row = o_off + p * 16 + ((lane >> 4) & 1) * 8 + (lane & 7);
                uint32_t bd = bB + swz(row, kh * 2 + ((lane >> 3) & 1));
                uint32_t r[4];
                ldsm4(bd, r);
                bh[p * 2][0] = r[0]; bh[p * 2][1] = r[1];
                bh[p * 2 + 1][0] = r[2]; bh[p * 2 + 1][1] = r[3];
                ldsm4(bd + BREG, r);
                bl[p * 2][0] = r[0]; bl[p * 2][1] = r[1];
                bl[p * 2 + 1][0] = r[2]; bl[p * 2 + 1][1] = r[3];
            }
            // term-major: same-accumulator reuse distance = MT*NT mmas
            #pragma unroll
            for (int mt = 0; mt < MT; mt++)
                #pragma unroll
                for (int nt = 0; nt < NT; nt++) mma_bf(acc[mt][nt], ah[mt], bh[nt]);
            #pragma unroll
            for (int mt = 0; mt < MT; mt++)
                #pragma unroll
                for (int nt = 0; nt < NT; nt++) mma_bf(acc[mt][nt], al[mt], bh[nt]);
            #pragma unroll
            for (int mt = 0; mt < MT; mt++)
                #pragma unroll
                for (int nt = 0; nt < NT; nt++) mma_bf(acc[mt][nt], ah[mt], bl[nt]);
        }
    };

    // 2-stage cp.async pipeline, one __syncthreads per chunk:
    //   wait(copy t) -> sync (publishes stage s; proves stage s^1 compute done)
    //   -> issue copy(t+1) into s^1 -> compute(s)
    copyAB(0, 0);
    for (int t = 0; t < T; t++) {
        int s = t & 1;
        CP_WAIT0();
        __syncthreads();
        if (t + 1 < T) copyAB(t + 1, s ^ 1);
        compute(s);
    }

    // epilogue (acc regs only)
    #pragma unroll
    for (int mt = 0; mt < MT; mt++) {
        int r0 = n0 + m_off + mt * 16 + (lane >> 2);
        #pragma unroll
        for (int nt = 0; nt < NT; nt++) {
            int cl = o_off + nt * 8 + (lane & 3) * 2;
            float b0v = s_bias[cl], b1v = s_bias[cl + 1];
            #pragma unroll
            for (int q = 0; q < 2; q++) {
                int r = r0 + q * 8;
                float vx = acc[mt][nt][q * 2 + 0] + b0v;
                float vy = acc[mt][nt][q * 2 + 1] + b1v;
                if (RELU) { vx = fmaxf(vx, 0.f); vy = fmaxf(vy, 0.f); }
                size_t ei = ((size_t)g * NN + r) * O + o0 + cl;
                if (RRES) {
                    __nv_bfloat162 ph = *(const __nv_bfloat162*)(resH + ei);
                    __nv_bfloat162 pl = *(const __nv_bfloat162*)(resL + ei);
                    vx += __bfloat162float(ph.x) + __bfloat162float(pl.x);
                    vy += __bfloat162float(ph.y) + __bfloat162float(pl.y);
                }
                if (WF32) *(float2*)(outF + ei) = make_float2(vx, vy);
                if (WSPLIT) {
                    float hx = __bfloat162float(__float2bfloat16(vx));
                    float hy = __bfloat162float(__float2bfloat16(vy));
                    *(uint32_t*)(outH + ei) = pk2(hx, hy);
                    *(uint32_t*)(outL + ei) = pk2(vx - hx, vy - hy);
                }
            }
        }
    }
}

// ---------------- epilogue: residual + mean + norms + output ----------------
// out layout: [ feats_inv (N*32) | feats_eqv (N*32*G) ]
__global__ void k_final(const float* __restrict__ feats, float* __restrict__ out) {
    const int n   = blockIdx.x;
    const int tid = threadIdx.x;   // 256 threads
    __shared__ float s_eqv[32][GG];
    __shared__ float s_inv[32];
    __shared__ float s_ng[GG];
    __shared__ float s_ninv;

    for (int idx = tid; idx < 32 * GG; idx += 256) {
        int c = idx / GG;
        int g = idx % GG;
        s_eqv[c][g] = g_E[((size_t)g * NN + n) * 32 + c] + feats[(n * 32 + c) * GG + g];
    }
    __syncthreads();

    if (tid < 32) {
        float sum = 0.0f;
        #pragma unroll 4
        for (int g = 0; g < GG; g++) sum += s_eqv[tid][g];
        s_inv[tid] = sum * (1.0f / GG);
    }
    if (tid >= 64 && tid < 64 + GG) {
        int g = tid - 64;
        float q = 0.0f;
        #pragma unroll
        for (int c = 0; c < 32; c++) { float v = s_eqv[c][g]; q += v * v; }
        s_ng[g] = fmaxf(sqrtf(q), 1e-4f);
    }
    __syncthreads();
    if (tid == 0) {
        float q = 0.0f;
        #pragma unroll
        for (int c = 0; c < 32; c++) q += s_inv[c] * s_inv[c];
        s_ninv = fmaxf(sqrtf(q), 1e-4f);
    }
    __syncthreads();

    if (tid < 32) out[n * 32 + tid] = s_inv[tid] / s_ninv;
    for (int idx = tid; idx < 32 * GG; idx += 256) {
        int c = idx / GG;
        int g = idx % GG;
        out[NN * 32 + (n * 32 + c) * GG + g] = s_eqv[c][g] / s_ng[g];
    }
}

// ---------------- launch (single stream, linear graph) ----------------
extern "C" void kernel_launch(void* const* d_in, const int* in_sizes, int n_in,
                              void* d_out, int out_size) {
    const float* feats = (const float*)d_in[0];
    const int*   nei   = (const int*)  d_in[1];
    const float* W_in  = (const float*)d_in[2];
    const float* b_in  = (const float*)d_in[3];
    const float* W_r1  = (const float*)d_in[4];
    const float* b_r1  = (const float*)d_in[5];
    const float* W_r2  = (const float*)d_in[6];
    const float* b_r2  = (const float*)d_in[7];
    const float* W_out = (const float*)d_in[8];
    const float* b_out = (const float*)d_in[9];
    float* out = (float*)d_out;

    void *pE, *pXh, *pXl, *pHh, *pHl, *pRh, *pRl;
    void *pBh_in, *pBl_in, *pBh_r1, *pBl_r1, *pBh_r2, *pBl_r2, *pBh_out, *pBl_out;
    cudaGetSymbolAddress(&pE,  g_E);
    cudaGetSymbolAddress(&pXh, g_Xh);  cudaGetSymbolAddress(&pXl, g_Xl);
    cudaGetSymbolAddress(&pHh, g_Hh);  cudaGetSymbolAddress(&pHl, g_Hl);
    cudaGetSymbolAddress(&pRh, g_Rh);  cudaGetSymbolAddress(&pRl, g_Rl);
    cudaGetSymbolAddress(&pBh_in,  g_Bh_in);   cudaGetSymbolAddress(&pBl_in,  g_Bl_in);
    cudaGetSymbolAddress(&pBh_r1,  g_Bh_r1);   cudaGetSymbolAddress(&pBl_r1,  g_Bl_r1);
    cudaGetSymbolAddress(&pBh_r2,  g_Bh_r2);   cudaGetSymbolAddress(&pBl_r2,  g_Bl_r2);
    cudaGetSymbolAddress(&pBh_out, g_Bh_out);  cudaGetSymbolAddress(&pBl_out, g_Bl_out);

    const int SMA = 2 * (2 * 64 * 64 + 2 * 128 * 64);   // 49152 (64x128 tiles)
    const int SMO = 2 * (2 * 128 * 64 + 2 * 32 * 64);   // 40960 (128x32 tile)
    cudaFuncSetAttribute((const void*)k_gemm<32, 256, 64, 128, false, false, false, true>,
                         cudaFuncAttributeMaxDynamicSharedMemorySize, SMA);
    cudaFuncSetAttribute((const void*)k_gemm<256, 512, 64, 128, true, false, false, true>,
                         cudaFuncAttributeMaxDynamicSharedMemorySize, SMA);
    cudaFuncSetAttribute((const void*)k_gemm<512, 256, 64, 128, false, false, true, true>,
                         cudaFuncAttributeMaxDynamicSharedMemorySize, SMA);
    cudaFuncSetAttribute((const void*)k_gemm<256, 32, 128, 32, false, true, false, false>,
                         cudaFuncAttributeMaxDynamicSharedMemorySize, SMO);

    // 1. fused prep: feats split + all four weight splits (one launch)
    {
        int total = GG * NN * 32
                  + (256 * 32 + 512 * 256 + 256 * 512 + 32 * 256) * KKN;
        k_prep<<<(total + 255) / 256, 256>>>(feats, W_in, W_r1, W_r2, W_out);
    }
    // 2. in: Hh/Hl = split(comb(X, W_in) + b_in)
    k_gemm<32, 256, 64, 128, false, false, false, true><<<dim3(8, 2, GG), 128, SMA>>>(
        (const __nv_bfloat16*)pXh, (const __nv_bfloat16*)pXl,
        (const __nv_bfloat16*)pBh_in, (const __nv_bfloat16*)pBl_in,
        b_in, nei, nullptr, nullptr, nullptr,
        (__nv_bfloat16*)pHh, (__nv_bfloat16*)pHl);
    // 3. r1: Rh/Rl = split(relu(comb(H, W_r1) + b_r1))
    k_gemm<256, 512, 64, 128, true, false, false, true><<<dim3(8, 4, GG), 128, SMA>>>(
        (const __nv_bfloat16*)pHh, (const __nv_bfloat16*)pHl,
        (const __nv_bfloat16*)pBh_r1, (const __nv_bfloat16*)pBl_r1,
        b_r1, nei, nullptr, nullptr, nullptr,
        (__nv_bfloat16*)pRh, (__nv_bfloat16*)pRl);
    // 4. r2: Hh/Hl = split((Hh+Hl) + comb(R, W_r2) + b_r2)   (in-place residual)
    k_gemm<512, 256, 64, 128, false, false, true, true><<<dim3(8, 2, GG), 128, SMA>>>(
        (const __nv_bfloat16*)pRh, (const __nv_bfloat16*)pRl,
        (const __nv_bfloat16*)pBh_r2, (const __nv_bfloat16*)pBl_r2,
        b_r2, nei, nullptr,
        (const __nv_bfloat16*)pHh, (const __nv_bfloat16*)pHl,
        (__nv_bfloat16*)pHh, (__nv_bfloat16*)pHl);
    // 5. out: E = comb(Hnew, W_out) + b_out (fp32)
    k_gemm<256, 32, 128, 32, false, true, false, false><<<dim3(4, 1, GG), 128, SMO>>>(
        (const __nv_bfloat16*)pHh, (const __nv_bfloat16*)pHl,
        (const __nv_bfloat16*)pBh_out, (const __nv_bfloat16*)pBl_out,
        b_out, nei, (float*)pE, nullptr, nullptr, nullptr, nullptr);
    // 6. final: residual + mean + norms
    k_final<<<NN, 256>>>(feats, out);
}